// round 12
// baseline (speedup 1.0000x reference)
#include <cuda_runtime.h>
#include <cuda_bf16.h>
#include <math.h>
#include <cstdint>

// ---------------------------------------------------------------------------
// Problem constants
// ---------------------------------------------------------------------------
#define NB   128          // batch N
#define CC   64           // channels C = O
#define TT   64           // T
#define VV   25           // V
#define PP   (TT*VV)      // 1600 positions per (n, channel)
#define SS   3            // spatial heads
#define NTV  (NB*TT*VV)   // 204800 samples per channel for BN

// weight-split segment offsets (elements)
#define WO_QKS  0          // 96*64   = 6144
#define WO_OUTS 6144       // 64*192  = 12288
#define WO_FFS  18432      // 64*64   = 4096
#define WO_OUTT 22528      // 64*256  = 16384
#define WO_FFT  38912      // 64*64   = 4096
#define WO_TCN  43008      // 64*448  = 28672
#define W_TOTAL 71680

// ---------------------------------------------------------------------------
// Scratch (device globals; no allocation allowed)
// ---------------------------------------------------------------------------
__device__ float g_qk  [ (size_t)NB*96*PP ];        // spatial qk conv out
__device__ float g_y   [ (size_t)NB*192*PP ];       // spatial attended
__device__ float g_conv[ (size_t)NB*CC*PP ];        // generic conv output
__device__ float g_sout[ (size_t)NB*CC*PP ];        // s_out == t_in
__device__ float g_b1  [ (size_t)NB*CC*PP ];
__device__ float g_b2  [ (size_t)NB*CC*PP ];
__device__ float g_xbar[ (size_t)NB*CC*TT ];        // mean over V
__device__ float g_qkt [ (size_t)NB*128*TT ];
__device__ float g_attt[ (size_t)NB*4*TT*TT ];      // 4 slots: f0,f1,b0,b1
__device__ float g_z   [ (size_t)NB*256*PP ];       // temporal attended
__device__ float g_stats[5*128];                    // 5 BNs x (sum[64], sumsq[64])
__device__ unsigned g_whi[W_TOTAL];                 // tf32 hi of all weights
__device__ unsigned g_wlo[W_TOTAL];                 // tf32 lo of all weights

// ---------------------------------------------------------------------------
// cp.async helpers
// ---------------------------------------------------------------------------
__device__ __forceinline__ unsigned int smem_u32(const void* p)
{
    return (unsigned int)__cvta_generic_to_shared(p);
}
__device__ __forceinline__ void cp16(unsigned int dst, const void* src, int sbytes)
{
    asm volatile("cp.async.cg.shared.global [%0], [%1], 16, %2;"
                 :: "r"(dst), "l"(src), "r"(sbytes));
}
__device__ __forceinline__ void cp4(unsigned int dst, const void* src, int sbytes)
{
    asm volatile("cp.async.ca.shared.global [%0], [%1], 4, %2;"
                 :: "r"(dst), "l"(src), "r"(sbytes));
}
__device__ __forceinline__ void cp_commit()
{
    asm volatile("cp.async.commit_group;");
}
template<int N>
__device__ __forceinline__ void cp_wait()
{
    asm volatile("cp.async.wait_group %0;" :: "n"(N));
}

// ---------------------------------------------------------------------------
// tf32 helpers
// ---------------------------------------------------------------------------
__device__ __forceinline__ void split_tf32(float x, unsigned& hi, unsigned& lo)
{
    asm("cvt.rna.tf32.f32 %0, %1;" : "=r"(hi) : "f"(x));
    float r = x - __uint_as_float(hi);
    asm("cvt.rna.tf32.f32 %0, %1;" : "=r"(lo) : "f"(r));
}
__device__ __forceinline__ void mma_tf32(float* c, const unsigned* a,
                                         unsigned b0, unsigned b1)
{
    asm volatile(
        "mma.sync.aligned.m16n8k8.row.col.f32.tf32.tf32.f32 "
        "{%0,%1,%2,%3}, {%4,%5,%6,%7}, {%8,%9}, {%0,%1,%2,%3};"
        : "+f"(c[0]), "+f"(c[1]), "+f"(c[2]), "+f"(c[3])
        : "r"(a[0]), "r"(a[1]), "r"(a[2]), "r"(a[3]), "r"(b0), "r"(b1));
}
__device__ __forceinline__ float tanh_fast(float x)
{
    float y;
    asm("tanh.approx.f32 %0, %1;" : "=f"(y) : "f"(x));
    return y;
}

// ---------------------------------------------------------------------------
// Weight pre-split: one-time hi/lo decomposition of all 6 weight matrices.
// grid (112, 6): blockIdx.y selects the segment.
// ---------------------------------------------------------------------------
__global__ void split_weights(
    const float* w0, const float* w1, const float* w2,
    const float* w3, const float* w4, const float* w5,
    unsigned* whi, unsigned* wlo)
{
    const int seg = blockIdx.y;
    const float* src; int n, off;
    switch (seg) {
        case 0: src = w0; n = 6144;  off = WO_QKS;  break;
        case 1: src = w1; n = 12288; off = WO_OUTS; break;
        case 2: src = w2; n = 4096;  off = WO_FFS;  break;
        case 3: src = w3; n = 16384; off = WO_OUTT; break;
        case 4: src = w4; n = 4096;  off = WO_FFT;  break;
        default: src = w5; n = 28672; off = WO_TCN; break;
    }
    int i = blockIdx.x * blockDim.x + threadIdx.x;
    if (i < n) {
        unsigned hi, lo;
        split_tf32(src[i], hi, lo);
        whi[off + i] = hi;
        wlo[off + i] = lo;
    }
}

// ---------------------------------------------------------------------------
// Tensor-core GEMM (3xTF32) with PRE-SPLIT weights.
//   Y[n][m][p] = sum_k A[m][k] * B[k][p]      (per n)
// A supplied as hi/lo tf32 arrays (from split_weights); B split in-loop.
// Tile: BM=64, BN=128, BK=16; 256 threads = 8 warps (2m x 4n of 32x32 tiles).
// cp.async double buffering for B; fused BN stats (bias must be nullptr).
// Phantom columns (p0+p >= P) stay zero (cp.async zfill) -> clean stats.
// ---------------------------------------------------------------------------
template<int TCN>
__global__ __launch_bounds__(256, 2) void sgemm_tf32(
    const float* __restrict__ X,
    const unsigned* __restrict__ Whi, const unsigned* __restrict__ Wlo,
    const float* __restrict__ bias, float* __restrict__ Y,
    int CIN, int COUT, float* __restrict__ stats)
{
    const int P  = PP;
    const int n  = blockIdx.z;
    const int m0 = blockIdx.y * 64;
    const int p0 = blockIdx.x * 128;
    const float* Xn = X + (size_t)n * (TCN ? 64 : CIN) * P;
    float*       Yn = Y + (size_t)n * COUT * P;

    __shared__ __align__(16) unsigned Ahi[2][64][20];
    __shared__ __align__(16) unsigned Alo[2][64][20];
    __shared__ __align__(16) float    Bs [2][16][132];

    float acc[2][4][4];
    #pragma unroll
    for (int i = 0; i < 2; i++)
        #pragma unroll
        for (int j = 0; j < 4; j++)
            #pragma unroll
            for (int c = 0; c < 4; c++) acc[i][j][c] = 0.f;

    const int lane = threadIdx.x & 31;
    const int warp = threadIdx.x >> 5;
    const int g    = lane >> 2;
    const int t4   = lane & 3;
    const int wm   = warp >> 2;   // 0..1
    const int wn   = warp & 3;    // 0..3

    const int nk = CIN / 16;
    unsigned pah[4], pal[4];

    auto issueB = [&](int kt, int buf) {
        const int k0 = kt * 16;
        if (!TCN) {
            #pragma unroll
            for (int i = 0; i < 2; i++) {
                int f = threadIdx.x + i * 256;
                int k = f >> 5, p = (f & 31) * 4;
                bool ok = (p0 + p) < P;
                const float* src = ok ? &Xn[(size_t)(k0 + k) * P + p0 + p] : Xn;
                cp16(smem_u32(&Bs[buf][k][p]), src, ok ? 16 : 0);
            }
        } else {
            #pragma unroll
            for (int i = 0; i < 8; i++) {
                int idx = threadIdx.x + i * 256;
                int k = idx >> 7, p = idx & 127;
                int kk = k0 + k;
                int c = kk / 7, dt = kk % 7;
                int src = p0 + p + (dt - 3) * 25;
                bool ok = (p0 + p) < P && src >= 0 && src < P;
                const float* sp = ok ? &Xn[(size_t)c * P + src] : Xn;
                cp4(smem_u32(&Bs[buf][k][p]), sp, ok ? 4 : 0);
            }
        }
        cp_commit();
    };

    // ---- prologue: tile 0 ----
    #pragma unroll
    for (int i = 0; i < 4; i++) {
        int idx = threadIdx.x + i * 256;
        int m = idx >> 4, k = idx & 15;
        unsigned h = 0u, l = 0u;
        if (m0 + m < COUT) {
            size_t o = (size_t)(m0 + m) * CIN + k;
            h = Whi[o]; l = Wlo[o];
        }
        Ahi[0][m][k] = h; Alo[0][m][k] = l;
    }
    issueB(0, 0);

    for (int it = 0; it < nk; it++) {
        const int cur = it & 1;
        const int nxt = 1 - cur;
        const bool more = (it + 1 < nk);

        if (more) {
            issueB(it + 1, nxt);
            const int k0n = (it + 1) * 16;
            #pragma unroll
            for (int i = 0; i < 4; i++) {
                int idx = threadIdx.x + i * 256;
                int m = idx >> 4, k = idx & 15;
                unsigned h = 0u, l = 0u;
                if (m0 + m < COUT) {
                    size_t o = (size_t)(m0 + m) * CIN + k0n + k;
                    h = Whi[o]; l = Wlo[o];
                }
                pah[i] = h; pal[i] = l;
            }
        }

        if (more) cp_wait<1>(); else cp_wait<0>();
        __syncthreads();

        // ---- compute current tile: 2 x k8 steps ----
        #pragma unroll
        for (int ks = 0; ks < 2; ks++) {
            const int kk = ks * 8;
            unsigned ahi[2][4], alo[2][4];
            #pragma unroll
            for (int mf = 0; mf < 2; mf++) {
                int r = wm * 32 + mf * 16 + g;
                ahi[mf][0] = Ahi[cur][r    ][kk + t4];
                ahi[mf][1] = Ahi[cur][r + 8][kk + t4];
                ahi[mf][2] = Ahi[cur][r    ][kk + t4 + 4];
                ahi[mf][3] = Ahi[cur][r + 8][kk + t4 + 4];
                alo[mf][0] = Alo[cur][r    ][kk + t4];
                alo[mf][1] = Alo[cur][r + 8][kk + t4];
                alo[mf][2] = Alo[cur][r    ][kk + t4 + 4];
                alo[mf][3] = Alo[cur][r + 8][kk + t4 + 4];
            }
            #pragma unroll
            for (int nf = 0; nf < 4; nf++) {
                int col = wn * 32 + nf * 8 + g;
                float b0 = Bs[cur][kk + t4    ][col];
                float b1 = Bs[cur][kk + t4 + 4][col];
                unsigned bh0, bl0, bh1, bl1;
                split_tf32(b0, bh0, bl0);
                split_tf32(b1, bh1, bl1);
                #pragma unroll
                for (int mf = 0; mf < 2; mf++) {
                    mma_tf32(acc[mf][nf], ahi[mf], bh0, bh1);
                    mma_tf32(acc[mf][nf], ahi[mf], bl0, bl1);
                    mma_tf32(acc[mf][nf], alo[mf], bh0, bh1);
                }
            }
        }

        if (more) {
            #pragma unroll
            for (int i = 0; i < 4; i++) {
                int idx = threadIdx.x + i * 256;
                int m = idx >> 4, k = idx & 15;
                Ahi[nxt][m][k] = pah[i];
                Alo[nxt][m][k] = pal[i];
            }
        }
        __syncthreads();
    }

    // ---- epilogue ----
    #pragma unroll
    for (int mf = 0; mf < 2; mf++) {
        #pragma unroll
        for (int half = 0; half < 2; half++) {
            int m = m0 + wm * 32 + mf * 16 + g + half * 8;
            if (m < COUT) {
                float bv = bias ? bias[m] : 0.f;
                #pragma unroll
                for (int nf = 0; nf < 4; nf++) {
                    int p = p0 + wn * 32 + nf * 8 + 2 * t4;
                    if (p < P) {
                        float2 v;
                        v.x = acc[mf][nf][half * 2 + 0] + bv;
                        v.y = acc[mf][nf][half * 2 + 1] + bv;
                        *(float2*)&Yn[(size_t)m * P + p] = v;
                    }
                }
            }
        }
    }
    if (stats) {
        #pragma unroll
        for (int mf = 0; mf < 2; mf++) {
            #pragma unroll
            for (int half = 0; half < 2; half++) {
                int m = m0 + wm * 32 + mf * 16 + g + half * 8;
                float s = 0.f, s2 = 0.f;
                #pragma unroll
                for (int nf = 0; nf < 4; nf++) {
                    float v0 = acc[mf][nf][half * 2 + 0];
                    float v1 = acc[mf][nf][half * 2 + 1];
                    s  += v0 + v1;
                    s2 += v0 * v0 + v1 * v1;
                }
                s  += __shfl_down_sync(0xffffffffu, s,  1, 4);
                s  += __shfl_down_sync(0xffffffffu, s,  2, 4);
                s2 += __shfl_down_sync(0xffffffffu, s2, 1, 4);
                s2 += __shfl_down_sync(0xffffffffu, s2, 2, 4);
                if (t4 == 0 && m < COUT) {
                    atomicAdd(&stats[m], s);
                    atomicAdd(&stats[64 + m], s2);
                }
            }
        }
    }
}

// ---------------------------------------------------------------------------
// Small GEMM for qk_t (P=64 columns only).
// ---------------------------------------------------------------------------
__global__ __launch_bounds__(256) void sgemm_small(
    const float* __restrict__ X, const float* __restrict__ W,
    const float* __restrict__ bias, float* __restrict__ Y,
    int CIN, int COUT, int P)
{
    const int n  = blockIdx.z;
    const int m0 = blockIdx.y * 64;
    const float* Xn = X + (size_t)n * CIN * P;
    float*       Yn = Y + (size_t)n * COUT * P;

    __shared__ float As[16][68];
    __shared__ float Bs[16][68];
    float acc[4][4];
    #pragma unroll
    for (int i = 0; i < 4; i++)
        #pragma unroll
        for (int j = 0; j < 4; j++) acc[i][j] = 0.f;

    const int tx = threadIdx.x & 15;
    const int ty = threadIdx.x >> 4;

    for (int k0 = 0; k0 < CIN; k0 += 16) {
        for (int i = threadIdx.x; i < 64 * 16; i += 256) {
            int m = i >> 4, k = i & 15;
            float w = 0.f;
            if (m0 + m < COUT) w = W[(size_t)(m0 + m) * CIN + k0 + k];
            As[k][m] = w;
        }
        for (int i = threadIdx.x; i < 16 * 64; i += 256) {
            int k = i >> 6, p = i & 63;
            Bs[k][p] = (p < P) ? Xn[(size_t)(k0 + k) * P + p] : 0.f;
        }
        __syncthreads();
        #pragma unroll
        for (int k = 0; k < 16; k++) {
            float a[4], b[4];
            #pragma unroll
            for (int i = 0; i < 4; i++) a[i] = As[k][ty * 4 + i];
            #pragma unroll
            for (int j = 0; j < 4; j++) b[j] = Bs[k][tx * 4 + j];
            #pragma unroll
            for (int i = 0; i < 4; i++)
                #pragma unroll
                for (int j = 0; j < 4; j++) acc[i][j] += a[i] * b[j];
        }
        __syncthreads();
    }
    #pragma unroll
    for (int i = 0; i < 4; i++) {
        int m = m0 + ty * 4 + i;
        if (m < COUT) {
            float bv = bias ? bias[m] : 0.f;
            #pragma unroll
            for (int j = 0; j < 4; j++) {
                int p = tx * 4 + j;
                if (p < P) Yn[(size_t)m * P + p] = acc[i][j] + bv;
            }
        }
    }
}

// ---------------------------------------------------------------------------
// Fused spatial attention + apply: one block per (n,t).
// ---------------------------------------------------------------------------
__global__ __launch_bounds__(256) void spatial_fused(
    const float* __restrict__ x, const float* __restrict__ qk,
    const float* __restrict__ att0, const float* __restrict__ alphas,
    float* __restrict__ y)
{
    int b = blockIdx.x;
    int t = b % TT; int n = b / TT;
    __shared__ float qs[3][16][25];
    __shared__ float ks[3][16][25];
    __shared__ float xs[25][68];       // [u][c]
    __shared__ float as[3][25][26];    // [s][u][v]

    const float* base = qk + (size_t)n * 96 * PP + t * VV;
    for (int i = threadIdx.x; i < 48 * 25; i += 256) {
        int c = i / 25, u = i % 25;
        qs[c >> 4][c & 15][u] = base[(size_t)c * PP + u];
        ks[c >> 4][c & 15][u] = base[(size_t)(48 + c) * PP + u];
    }
    const float* xb = x + (size_t)n * CC * PP + t * VV;
    for (int i = threadIdx.x; i < 64 * 25; i += 256) {
        int c = i / 25, u = i % 25;
        xs[u][c] = xb[(size_t)c * PP + u];
    }
    __syncthreads();

    for (int i = threadIdx.x; i < 3 * 625; i += 256) {
        int s = i / 625, r = i % 625;
        int u = r / 25, v = r % 25;
        float d = 0.f;
        #pragma unroll
        for (int c = 0; c < 16; c++) d += qs[s][c][u] * ks[s][c][v];
        as[s][u][v] = att0[(size_t)s * 625 + r] + tanh_fast(d * (1.f / 16.f)) * alphas[s];
    }
    __syncthreads();

    if (threadIdx.x >= 240) return;
    int s  = threadIdx.x / 80;
    int r  = threadIdx.x % 80;
    int cg = r / 5;
    int vg = r % 5;
    float acc[4][5];
    #pragma unroll
    for (int i = 0; i < 4; i++)
        #pragma unroll
        for (int j = 0; j < 5; j++) acc[i][j] = 0.f;
    #pragma unroll
    for (int u = 0; u < 25; u++) {
        float a[4], bb[5];
        #pragma unroll
        for (int i = 0; i < 4; i++) a[i] = xs[u][cg * 4 + i];
        #pragma unroll
        for (int j = 0; j < 5; j++) bb[j] = as[s][u][vg * 5 + j];
        #pragma unroll
        for (int i = 0; i < 4; i++)
            #pragma unroll
            for (int j = 0; j < 5; j++) acc[i][j] += a[i] * bb[j];
    }
    float* yb = y + (size_t)n * 192 * PP + t * VV;
    #pragma unroll
    for (int i = 0; i < 4; i++) {
        float* yp = yb + (size_t)(s * 64 + cg * 4 + i) * PP + vg * 5;
        #pragma unroll
        for (int j = 0; j < 5; j++) yp[j] = acc[i][j];
    }
}

__global__ void zero_stats_kernel(float* s)
{
    int i = blockIdx.x * blockDim.x + threadIdx.x;
    if (i < 5 * 128) s[i] = 0.f;
}

// out = leaky( res + gamma_c*(conv-mu_c)*rsqrt(var_c+eps) + beta_c ), float4
__global__ __launch_bounds__(256) void bn_apply(
    const float4* __restrict__ conv, const float4* __restrict__ res,
    const float* __restrict__ gamma, const float* __restrict__ beta,
    const float* __restrict__ stats, float4* __restrict__ out)
{
    size_t i = (size_t)blockIdx.x * blockDim.x + threadIdx.x;
    const size_t TOT4 = (size_t)NB * CC * PP / 4;
    if (i >= TOT4) return;
    int c = (int)((i / (PP / 4)) & 63);
    float mu  = stats[c] * (1.f / (float)NTV);
    float var = stats[64 + c] * (1.f / (float)NTV) - mu * mu;
    float g = gamma[c] * rsqrtf(var + 1e-5f);
    float sh = beta[c] - mu * g;
    float4 cv = conv[i], rv = res[i], o;
    float v;
    v = rv.x + cv.x * g + sh; o.x = v > 0.f ? v : 0.1f * v;
    v = rv.y + cv.y * g + sh; o.y = v > 0.f ? v : 0.1f * v;
    v = rv.z + cv.z * g + sh; o.z = v > 0.f ? v : 0.1f * v;
    v = rv.w + cv.w * g + sh; o.w = v > 0.f ? v : 0.1f * v;
    out[i] = o;
}

// ---------------------------------------------------------------------------
// Temporal path
// ---------------------------------------------------------------------------
__global__ void mean_v_kernel(const float* __restrict__ X, float* __restrict__ xb)
{
    int i = blockIdx.x * blockDim.x + threadIdx.x;  // over N*C*T
    if (i >= NB * CC * TT) return;
    const float* p = X + (size_t)i * VV;
    float s = 0.f;
    #pragma unroll
    for (int v = 0; v < VV; v++) s += p[v];
    xb[i] = s * (1.f / (float)VV);
}

__global__ __launch_bounds__(256) void temporal_att(
    const float* __restrict__ qkt, const float* __restrict__ alphaf,
    const float* __restrict__ alphab, float* __restrict__ attt)
{
    int b = blockIdx.x;
    int slot = b & 3; int n = b >> 2;
    int dir = slot >> 1, s = slot & 1;
    int qg = (dir == 0) ? s : 2 + s;
    int kg = (dir == 0) ? 4 + s : 6 + s;
    __shared__ float qs[16][64], ks2[16][64];
    const float* base = qkt + (size_t)n * 128 * TT;
    for (int i = threadIdx.x; i < 16 * 64; i += 256) {
        int c = i >> 6, t = i & 63;
        qs [c][t] = base[(size_t)(qg * 16 + c) * TT + t];
        ks2[c][t] = base[(size_t)(kg * 16 + c) * TT + t];
    }
    __syncthreads();
    float alpha = (dir == 0) ? alphaf[s] : alphab[s];
    float* outp = attt + ((size_t)n * 4 + slot) * TT * TT;
    for (int i = threadIdx.x; i < TT * TT; i += 256) {
        int t = i >> 6, q = i & 63;
        bool keep = (dir == 0) ? (t >= q) : (q >= t);
        float d = 0.f;
        #pragma unroll
        for (int c = 0; c < 16; c++) d += qs[c][t] * ks2[c][q];
        outp[i] = keep ? tanh_fast(d * (1.f / 16.f)) * alpha : 0.f;
    }
}

// z[n, chbase+c, q, v] = sum_t tin[n,c,t,v] * att[t,q]
__global__ __launch_bounds__(256) void temporal_apply(
    const float* __restrict__ tin, const float* __restrict__ attt,
    float* __restrict__ z)
{
    int b = blockIdx.x;
    int slot = b & 3; int n = b >> 2;
    int dir = slot >> 1, s = slot & 1;
    int chbase = dir * 128 + s * 64;
    __shared__ float as[64][65];
    const float* ap = attt + ((size_t)n * 4 + slot) * TT * TT;
    for (int i = threadIdx.x; i < TT * TT; i += 256) as[i >> 6][i & 63] = ap[i];
    __syncthreads();
    const float* tb = tin + (size_t)n * CC * PP;
    float*       zb = z   + (size_t)n * 256 * PP;
    for (int r = threadIdx.x; r < CC * VV; r += 256) {
        int c = r / 25, v = r % 25;
        float acc[64];
        #pragma unroll
        for (int q = 0; q < 64; q++) acc[q] = 0.f;
        const float* tp = tb + (size_t)c * PP + v;
        for (int t = 0; t < 64; t++) {
            float a = tp[t * 25];
            #pragma unroll
            for (int q = 0; q < 64; q++) acc[q] += a * as[t][q];
        }
        float* zp = zb + (size_t)(chbase + c) * PP + v;
        #pragma unroll
        for (int q = 0; q < 64; q++) zp[q * 25] = acc[q];
    }
}

// ---------------------------------------------------------------------------
// Launcher
// ---------------------------------------------------------------------------
static float* sym(const void* symbol)
{
    void* p = nullptr;
    cudaGetSymbolAddress(&p, symbol);
    return (float*)p;
}

extern "C" void kernel_launch(void* const* d_in, const int* in_sizes, int n_in,
                              void* d_out, int out_size)
{
    const float* x       = (const float*)d_in[0];
    const float* att0s   = (const float*)d_in[1];
    const float* alphas  = (const float*)d_in[2];
    const float* W_qk_s  = (const float*)d_in[3];
    const float* b_qk_s  = (const float*)d_in[4];
    const float* W_outs  = (const float*)d_in[5];
    const float* g_outs  = (const float*)d_in[7];
    const float* be_outs = (const float*)d_in[8];
    const float* W_ffs   = (const float*)d_in[9];
    const float* g_ffs   = (const float*)d_in[11];
    const float* be_ffs  = (const float*)d_in[12];
    const float* W_qk_t  = (const float*)d_in[13];
    const float* b_qk_t  = (const float*)d_in[14];
    const float* al_f    = (const float*)d_in[15];
    const float* al_b    = (const float*)d_in[16];
    const float* W_outt  = (const float*)d_in[17];
    const float* g_outt  = (const float*)d_in[19];
    const float* be_outt = (const float*)d_in[20];
    const float* W_fft   = (const float*)d_in[21];
    const float* g_fft   = (const float*)d_in[23];
    const float* be_fft  = (const float*)d_in[24];
    const float* W_tcn   = (const float*)d_in[25];
    const float* g_tcn   = (const float*)d_in[27];
    const float* be_tcn  = (const float*)d_in[28];
    float* out = (float*)d_out;

    float* p_qk   = sym(g_qk);
    float* p_y    = sym(g_y);
    float* p_conv = sym(g_conv);
    float* p_sout = sym(g_sout);
    float* p_b1   = sym(g_b1);
    float* p_b2   = sym(g_b2);
    float* p_xbar = sym(g_xbar);
    float* p_qkt  = sym(g_qkt);
    float* p_attt = sym(g_attt);
    float* p_z    = sym(g_z);
    float* p_st   = sym(g_stats);
    unsigned* p_whi = (unsigned*)sym(g_whi);
    unsigned* p_wlo = (unsigned*)sym(g_wlo);

    const size_t TOT = (size_t)NB * CC * PP;
    const int EW_BLOCKS4 = (int)((TOT / 4 + 255) / 256);
    const dim3 G13(13, 1, NB);

    zero_stats_kernel<<<3, 256>>>(p_st);
    split_weights<<<dim3(112, 6), 256>>>(W_qk_s, W_outs, W_ffs, W_outt, W_fft,
                                         W_tcn, p_whi, p_wlo);

    // --- spatial attention (fused att + apply) ---
    sgemm_tf32<0><<<dim3(13, 2, NB), 256>>>(x, p_whi + WO_QKS, p_wlo + WO_QKS,
                                            b_qk_s, p_qk, 64, 96, nullptr);
    spatial_fused<<<NB * TT, 256>>>(x, p_qk, att0s, alphas, p_y);

    // y = BN(conv(y, W_outs)); y = leaky(x + y)   [bias cancels in BN]
    sgemm_tf32<0><<<G13, 256>>>(p_y, p_whi + WO_OUTS, p_wlo + WO_OUTS,
                                nullptr, p_conv, 192, 64, p_st + 0);
    bn_apply<<<EW_BLOCKS4, 256>>>((const float4*)p_conv, (const float4*)x,
                                  g_outs, be_outs, p_st + 0, (float4*)p_b1);

    // y = BN(conv(y, W_ffs)); s_out = leaky(x + y)
    sgemm_tf32<0><<<G13, 256>>>(p_b1, p_whi + WO_FFS, p_wlo + WO_FFS,
                                nullptr, p_conv, 64, 64, p_st + 128);
    bn_apply<<<EW_BLOCKS4, 256>>>((const float4*)p_conv, (const float4*)x,
                                  g_ffs, be_ffs, p_st + 128, (float4*)p_sout);

    // --- temporal attention ---
    mean_v_kernel<<<(NB * CC * TT + 255) / 256, 256>>>(p_sout, p_xbar);
    sgemm_small<<<dim3(1, 2, NB), 256>>>(p_xbar, W_qk_t, b_qk_t, p_qkt, 64, 128, TT);
    temporal_att<<<NB * 4, 256>>>(p_qkt, al_f, al_b, p_attt);
    temporal_apply<<<NB * 4, 256>>>(p_sout, p_attt, p_z);

    // z = BN(conv(z, W_outt)); z = leaky(t_in + z)
    sgemm_tf32<0><<<G13, 256>>>(p_z, p_whi + WO_OUTT, p_wlo + WO_OUTT,
                                nullptr, p_conv, 256, 64, p_st + 256);
    bn_apply<<<EW_BLOCKS4, 256>>>((const float4*)p_conv, (const float4*)p_sout,
                                  g_outt, be_outt, p_st + 256, (float4*)p_b1);

    // z = BN(conv(z, W_fft)); z = leaky(t_in + z)
    sgemm_tf32<0><<<G13, 256>>>(p_b1, p_whi + WO_FFT, p_wlo + WO_FFT,
                                nullptr, p_conv, 64, 64, p_st + 384);
    bn_apply<<<EW_BLOCKS4, 256>>>((const float4*)p_conv, (const float4*)p_sout,
                                  g_fft, be_fft, p_st + 384, (float4*)p_b2);

    // --- TCN as K=448 GEMM (k = c*7+dt, shifted B rows) ---
    sgemm_tf32<1><<<G13, 256>>>(p_b2, p_whi + WO_TCN, p_wlo + WO_TCN,
                                nullptr, p_conv, 448, 64, p_st + 512);
    bn_apply<<<EW_BLOCKS4, 256>>>((const float4*)p_conv, (const float4*)p_b2,
                                  g_tcn, be_tcn, p_st + 512, (float4*)out);
}

// round 13
// speedup vs baseline: 1.0189x; 1.0189x over previous
#include <cuda_runtime.h>
#include <cuda_bf16.h>
#include <math.h>
#include <cstdint>

// ---------------------------------------------------------------------------
// Problem constants
// ---------------------------------------------------------------------------
#define NB   128          // batch N
#define CC   64           // channels C = O
#define TT   64           // T
#define VV   25           // V
#define PP   (TT*VV)      // 1600 positions per (n, channel)
#define SS   3            // spatial heads
#define NTV  (NB*TT*VV)   // 204800 samples per channel for BN

// ---------------------------------------------------------------------------
// Scratch (device globals; no allocation allowed)
// ---------------------------------------------------------------------------
__device__ float g_qk  [ (size_t)NB*96*PP ];        // spatial qk conv out
__device__ float g_y   [ (size_t)NB*192*PP ];       // spatial attended
__device__ float g_conv[ (size_t)NB*CC*PP ];        // generic conv output
__device__ float g_sout[ (size_t)NB*CC*PP ];        // s_out == t_in
__device__ float g_b1  [ (size_t)NB*CC*PP ];
__device__ float g_b2  [ (size_t)NB*CC*PP ];
__device__ float g_xbar[ (size_t)NB*CC*TT ];        // mean over V
__device__ float g_qkt [ (size_t)NB*128*TT ];
__device__ float g_attt[ (size_t)NB*4*TT*TT ];      // 4 slots: f0,f1,b0,b1
__device__ float g_z   [ (size_t)NB*256*PP ];       // temporal attended
__device__ float g_stats[5*128];                    // 5 BNs x (sum[64], sumsq[64])

// ---------------------------------------------------------------------------
// cp.async helpers
// ---------------------------------------------------------------------------
__device__ __forceinline__ unsigned int smem_u32(const void* p)
{
    return (unsigned int)__cvta_generic_to_shared(p);
}
__device__ __forceinline__ void cp16(unsigned int dst, const void* src, int sbytes)
{
    asm volatile("cp.async.cg.shared.global [%0], [%1], 16, %2;"
                 :: "r"(dst), "l"(src), "r"(sbytes));
}
__device__ __forceinline__ void cp4(unsigned int dst, const void* src, int sbytes)
{
    asm volatile("cp.async.ca.shared.global [%0], [%1], 4, %2;"
                 :: "r"(dst), "l"(src), "r"(sbytes));
}
__device__ __forceinline__ void cp_commit()
{
    asm volatile("cp.async.commit_group;");
}
template<int N>
__device__ __forceinline__ void cp_wait()
{
    asm volatile("cp.async.wait_group %0;" :: "n"(N));
}

// ---------------------------------------------------------------------------
// tf32 helpers (3xTF32 error-compensated path)
// ---------------------------------------------------------------------------
__device__ __forceinline__ void split_tf32(float x, unsigned& hi, unsigned& lo)
{
    asm("cvt.rna.tf32.f32 %0, %1;" : "=r"(hi) : "f"(x));
    float r = x - __uint_as_float(hi);
    asm("cvt.rna.tf32.f32 %0, %1;" : "=r"(lo) : "f"(r));
}
__device__ __forceinline__ void mma_tf32(float* c, const unsigned* a,
                                         unsigned b0, unsigned b1)
{
    asm volatile(
        "mma.sync.aligned.m16n8k8.row.col.f32.tf32.tf32.f32 "
        "{%0,%1,%2,%3}, {%4,%5,%6,%7}, {%8,%9}, {%0,%1,%2,%3};"
        : "+f"(c[0]), "+f"(c[1]), "+f"(c[2]), "+f"(c[3])
        : "r"(a[0]), "r"(a[1]), "r"(a[2]), "r"(a[3]), "r"(b0), "r"(b1));
}
__device__ __forceinline__ float tanh_fast(float x)
{
    float y;
    asm("tanh.approx.f32 %0, %1;" : "=f"(y) : "f"(x));
    return y;
}

// ---------------------------------------------------------------------------
// Tensor-core GEMM (3xTF32) for 1x1 convs and the TCN-as-GEMM.
//   Y[n][m][p] = sum_k A[m][k] * B[k][p]      (per n)
// TCN==0: A=W (COUT x CIN), B[k][p] = X[n][k][p]
// TCN==1: A=W_tcn flattened (64 x 448), k=(c*7+dt),
//         B[k][p] = X[n][c][p + (dt-3)*25] with zero fill out of range.
// Tile: BM=64, BN=128, BK=16; 256 threads = 8 warps in 2(m) x 4(n) grid of
// 32x32 warp tiles; mma.m16n8k8 tf32 with hi/lo 3-term decomposition
// (hi*hi + hi*lo + lo*hi) -> fp32-grade accuracy on the tensor pipe.
// As stored [m][k] padded to 20; Bs [k][132]. cp.async double buffering.
// grid: (13, ceil(COUT/64), NB)
// If stats != nullptr, fuses per-channel sum/sumsq (bias must be nullptr).
// Phantom columns (p0+p >= P) stay zero (cp.async zfill) -> clean stats.
// ---------------------------------------------------------------------------
template<int TCN>
__global__ __launch_bounds__(256, 2) void sgemm_tf32(
    const float* __restrict__ X, const float* __restrict__ W,
    const float* __restrict__ bias, float* __restrict__ Y,
    int CIN, int COUT, float* __restrict__ stats)
{
    const int P  = PP;
    const int n  = blockIdx.z;
    const int m0 = blockIdx.y * 64;
    const int p0 = blockIdx.x * 128;
    const float* Xn = X + (size_t)n * (TCN ? 64 : CIN) * P;
    float*       Yn = Y + (size_t)n * COUT * P;

    __shared__ __align__(16) float As[2][64][20];
    __shared__ __align__(16) float Bs[2][16][132];

    // acc[mf][nf][c]: mma fragment accumulators (2 m16-tiles x 4 n8-tiles)
    float acc[2][4][4];
    #pragma unroll
    for (int i = 0; i < 2; i++)
        #pragma unroll
        for (int j = 0; j < 4; j++)
            #pragma unroll
            for (int c = 0; c < 4; c++) acc[i][j][c] = 0.f;

    const int lane = threadIdx.x & 31;
    const int warp = threadIdx.x >> 5;
    const int g    = lane >> 2;   // groupID (row / col-group)
    const int t4   = lane & 3;    // threadID_in_group
    const int wm   = warp >> 2;   // 0..1 (m warp tile)
    const int wn   = warp & 3;    // 0..3 (n warp tile)

    const int nk = CIN / 16;
    float pa[4];

    // ---- issue B tile for k-tile `kt` into buffer `buf` via cp.async ----
    auto issueB = [&](int kt, int buf) {
        const int k0 = kt * 16;
        if (!TCN) {
            #pragma unroll
            for (int i = 0; i < 2; i++) {
                int f = threadIdx.x + i * 256;      // 0..511 float4 slots
                int k = f >> 5, p = (f & 31) * 4;
                bool ok = (p0 + p) < P;
                const float* src = ok ? &Xn[(size_t)(k0 + k) * P + p0 + p] : Xn;
                cp16(smem_u32(&Bs[buf][k][p]), src, ok ? 16 : 0);
            }
        } else {
            #pragma unroll
            for (int i = 0; i < 8; i++) {
                int idx = threadIdx.x + i * 256;    // 0..2047
                int k = idx >> 7, p = idx & 127;
                int kk = k0 + k;
                int c = kk / 7, dt = kk % 7;
                int src = p0 + p + (dt - 3) * 25;
                bool ok = (p0 + p) < P && src >= 0 && src < P;
                const float* sp = ok ? &Xn[(size_t)c * P + src] : Xn;
                cp4(smem_u32(&Bs[buf][k][p]), sp, ok ? 4 : 0);
            }
        }
        cp_commit();
    };

    // ---- prologue: tile 0 ----
    #pragma unroll
    for (int i = 0; i < 4; i++) {
        int idx = threadIdx.x + i * 256;   // 0..1023
        int m = idx >> 4, k = idx & 15;
        float w = 0.f;
        if (m0 + m < COUT) w = W[(size_t)(m0 + m) * CIN + k];
        As[0][m][k] = w;
    }
    issueB(0, 0);

    for (int it = 0; it < nk; it++) {
        const int cur = it & 1;
        const int nxt = 1 - cur;
        const bool more = (it + 1 < nk);

        if (more) {
            issueB(it + 1, nxt);
            const int k0n = (it + 1) * 16;
            #pragma unroll
            for (int i = 0; i < 4; i++) {
                int idx = threadIdx.x + i * 256;
                int m = idx >> 4, k = idx & 15;
                float w = 0.f;
                if (m0 + m < COUT) w = W[(size_t)(m0 + m) * CIN + k0n + k];
                pa[i] = w;
            }
        }

        if (more) cp_wait<1>(); else cp_wait<0>();
        __syncthreads();

        // ---- compute current tile: 2 x k8 steps ----
        #pragma unroll
        for (int ks = 0; ks < 2; ks++) {
            const int kk = ks * 8;
            unsigned ahi[2][4], alo[2][4];
            #pragma unroll
            for (int mf = 0; mf < 2; mf++) {
                int r = wm * 32 + mf * 16 + g;
                float a0 = As[cur][r    ][kk + t4];
                float a1 = As[cur][r + 8][kk + t4];
                float a2 = As[cur][r    ][kk + t4 + 4];
                float a3 = As[cur][r + 8][kk + t4 + 4];
                split_tf32(a0, ahi[mf][0], alo[mf][0]);
                split_tf32(a1, ahi[mf][1], alo[mf][1]);
                split_tf32(a2, ahi[mf][2], alo[mf][2]);
                split_tf32(a3, ahi[mf][3], alo[mf][3]);
            }
            #pragma unroll
            for (int nf = 0; nf < 4; nf++) {
                int col = wn * 32 + nf * 8 + g;
                float b0 = Bs[cur][kk + t4    ][col];
                float b1 = Bs[cur][kk + t4 + 4][col];
                unsigned bh0, bl0, bh1, bl1;
                split_tf32(b0, bh0, bl0);
                split_tf32(b1, bh1, bl1);
                #pragma unroll
                for (int mf = 0; mf < 2; mf++) {
                    mma_tf32(acc[mf][nf], ahi[mf], bh0, bh1);
                    mma_tf32(acc[mf][nf], ahi[mf], bl0, bl1);
                    mma_tf32(acc[mf][nf], alo[mf], bh0, bh1);
                }
            }
        }

        if (more) {
            #pragma unroll
            for (int i = 0; i < 4; i++) {
                int idx = threadIdx.x + i * 256;
                int m = idx >> 4, k = idx & 15;
                As[nxt][m][k] = pa[i];
            }
        }
        __syncthreads();
    }

    // ---- epilogue: fragment rows -> global ----
    #pragma unroll
    for (int mf = 0; mf < 2; mf++) {
        #pragma unroll
        for (int half = 0; half < 2; half++) {
            int m = m0 + wm * 32 + mf * 16 + g + half * 8;
            if (m < COUT) {
                float bv = bias ? bias[m] : 0.f;
                #pragma unroll
                for (int nf = 0; nf < 4; nf++) {
                    int p = p0 + wn * 32 + nf * 8 + 2 * t4;
                    if (p < P) {
                        float2 v;
                        v.x = acc[mf][nf][half * 2 + 0] + bv;
                        v.y = acc[mf][nf][half * 2 + 1] + bv;
                        *(float2*)&Yn[(size_t)m * P + p] = v;
                    }
                }
            }
        }
    }
    if (stats) {
        #pragma unroll
        for (int mf = 0; mf < 2; mf++) {
            #pragma unroll
            for (int half = 0; half < 2; half++) {
                int m = m0 + wm * 32 + mf * 16 + g + half * 8;
                float s = 0.f, s2 = 0.f;
                #pragma unroll
                for (int nf = 0; nf < 4; nf++) {
                    float v0 = acc[mf][nf][half * 2 + 0];
                    float v1 = acc[mf][nf][half * 2 + 1];
                    s  += v0 + v1;
                    s2 += v0 * v0 + v1 * v1;
                }
                // reduce across the 4 lanes (t4) sharing this fragment row
                s  += __shfl_down_sync(0xffffffffu, s,  1, 4);
                s  += __shfl_down_sync(0xffffffffu, s,  2, 4);
                s2 += __shfl_down_sync(0xffffffffu, s2, 1, 4);
                s2 += __shfl_down_sync(0xffffffffu, s2, 2, 4);
                if (t4 == 0 && m < COUT) {
                    atomicAdd(&stats[m], s);
                    atomicAdd(&stats[64 + m], s2);
                }
            }
        }
    }
}

// ---------------------------------------------------------------------------
// Small GEMM for qk_t (P=64 columns only).
// ---------------------------------------------------------------------------
__global__ __launch_bounds__(256) void sgemm_small(
    const float* __restrict__ X, const float* __restrict__ W,
    const float* __restrict__ bias, float* __restrict__ Y,
    int CIN, int COUT, int P)
{
    const int n  = blockIdx.z;
    const int m0 = blockIdx.y * 64;
    const float* Xn = X + (size_t)n * CIN * P;
    float*       Yn = Y + (size_t)n * COUT * P;

    __shared__ float As[16][68];
    __shared__ float Bs[16][68];
    float acc[4][4];
    #pragma unroll
    for (int i = 0; i < 4; i++)
        #pragma unroll
        for (int j = 0; j < 4; j++) acc[i][j] = 0.f;

    const int tx = threadIdx.x & 15;
    const int ty = threadIdx.x >> 4;

    for (int k0 = 0; k0 < CIN; k0 += 16) {
        for (int i = threadIdx.x; i < 64 * 16; i += 256) {
            int m = i >> 4, k = i & 15;
            float w = 0.f;
            if (m0 + m < COUT) w = W[(size_t)(m0 + m) * CIN + k0 + k];
            As[k][m] = w;
        }
        for (int i = threadIdx.x; i < 16 * 64; i += 256) {
            int k = i >> 6, p = i & 63;
            Bs[k][p] = (p < P) ? Xn[(size_t)(k0 + k) * P + p] : 0.f;
        }
        __syncthreads();
        #pragma unroll
        for (int k = 0; k < 16; k++) {
            float a[4], b[4];
            #pragma unroll
            for (int i = 0; i < 4; i++) a[i] = As[k][ty * 4 + i];
            #pragma unroll
            for (int j = 0; j < 4; j++) b[j] = Bs[k][tx * 4 + j];
            #pragma unroll
            for (int i = 0; i < 4; i++)
                #pragma unroll
                for (int j = 0; j < 4; j++) acc[i][j] += a[i] * b[j];
        }
        __syncthreads();
    }
    #pragma unroll
    for (int i = 0; i < 4; i++) {
        int m = m0 + ty * 4 + i;
        if (m < COUT) {
            float bv = bias ? bias[m] : 0.f;
            #pragma unroll
            for (int j = 0; j < 4; j++) {
                int p = tx * 4 + j;
                if (p < P) Yn[(size_t)m * P + p] = acc[i][j] + bv;
            }
        }
    }
}

// ---------------------------------------------------------------------------
// Fused spatial attention + apply: one block per (n,t).
// ---------------------------------------------------------------------------
__global__ __launch_bounds__(256) void spatial_fused(
    const float* __restrict__ x, const float* __restrict__ qk,
    const float* __restrict__ att0, const float* __restrict__ alphas,
    float* __restrict__ y)
{
    int b = blockIdx.x;
    int t = b % TT; int n = b / TT;
    __shared__ float qs[3][16][25];
    __shared__ float ks[3][16][25];
    __shared__ float xs[25][68];       // [u][c]
    __shared__ float as[3][25][26];    // [s][u][v]

    const float* base = qk + (size_t)n * 96 * PP + t * VV;
    for (int i = threadIdx.x; i < 48 * 25; i += 256) {
        int c = i / 25, u = i % 25;
        qs[c >> 4][c & 15][u] = base[(size_t)c * PP + u];
        ks[c >> 4][c & 15][u] = base[(size_t)(48 + c) * PP + u];
    }
    const float* xb = x + (size_t)n * CC * PP + t * VV;
    for (int i = threadIdx.x; i < 64 * 25; i += 256) {
        int c = i / 25, u = i % 25;
        xs[u][c] = xb[(size_t)c * PP + u];
    }
    __syncthreads();

    for (int i = threadIdx.x; i < 3 * 625; i += 256) {
        int s = i / 625, r = i % 625;
        int u = r / 25, v = r % 25;
        float d = 0.f;
        #pragma unroll
        for (int c = 0; c < 16; c++) d += qs[s][c][u] * ks[s][c][v];
        as[s][u][v] = att0[(size_t)s * 625 + r] + tanh_fast(d * (1.f / 16.f)) * alphas[s];
    }
    __syncthreads();

    if (threadIdx.x >= 240) return;
    int s  = threadIdx.x / 80;
    int r  = threadIdx.x % 80;
    int cg = r / 5;
    int vg = r % 5;
    float acc[4][5];
    #pragma unroll
    for (int i = 0; i < 4; i++)
        #pragma unroll
        for (int j = 0; j < 5; j++) acc[i][j] = 0.f;
    #pragma unroll
    for (int u = 0; u < 25; u++) {
        float a[4], bb[5];
        #pragma unroll
        for (int i = 0; i < 4; i++) a[i] = xs[u][cg * 4 + i];
        #pragma unroll
        for (int j = 0; j < 5; j++) bb[j] = as[s][u][vg * 5 + j];
        #pragma unroll
        for (int i = 0; i < 4; i++)
            #pragma unroll
            for (int j = 0; j < 5; j++) acc[i][j] += a[i] * bb[j];
    }
    float* yb = y + (size_t)n * 192 * PP + t * VV;
    #pragma unroll
    for (int i = 0; i < 4; i++) {
        float* yp = yb + (size_t)(s * 64 + cg * 4 + i) * PP + vg * 5;
        #pragma unroll
        for (int j = 0; j < 5; j++) yp[j] = acc[i][j];
    }
}

__global__ void zero_stats_kernel(float* s)
{
    int i = blockIdx.x * blockDim.x + threadIdx.x;
    if (i < 5 * 128) s[i] = 0.f;
}

// out = leaky( res + gamma_c*(conv-mu_c)*rsqrt(var_c+eps) + beta_c ), float4
__global__ __launch_bounds__(256) void bn_apply(
    const float4* __restrict__ conv, const float4* __restrict__ res,
    const float* __restrict__ gamma, const float* __restrict__ beta,
    const float* __restrict__ stats, float4* __restrict__ out)
{
    size_t i = (size_t)blockIdx.x * blockDim.x + threadIdx.x;
    const size_t TOT4 = (size_t)NB * CC * PP / 4;
    if (i >= TOT4) return;
    int c = (int)((i / (PP / 4)) & 63);
    float mu  = stats[c] * (1.f / (float)NTV);
    float var = stats[64 + c] * (1.f / (float)NTV) - mu * mu;
    float g = gamma[c] * rsqrtf(var + 1e-5f);
    float sh = beta[c] - mu * g;
    float4 cv = conv[i], rv = res[i], o;
    float v;
    v = rv.x + cv.x * g + sh; o.x = v > 0.f ? v : 0.1f * v;
    v = rv.y + cv.y * g + sh; o.y = v > 0.f ? v : 0.1f * v;
    v = rv.z + cv.z * g + sh; o.z = v > 0.f ? v : 0.1f * v;
    v = rv.w + cv.w * g + sh; o.w = v > 0.f ? v : 0.1f * v;
    out[i] = o;
}

// ---------------------------------------------------------------------------
// Temporal path
// ---------------------------------------------------------------------------
__global__ void mean_v_kernel(const float* __restrict__ X, float* __restrict__ xb)
{
    int i = blockIdx.x * blockDim.x + threadIdx.x;  // over N*C*T
    if (i >= NB * CC * TT) return;
    const float* p = X + (size_t)i * VV;
    float s = 0.f;
    #pragma unroll
    for (int v = 0; v < VV; v++) s += p[v];
    xb[i] = s * (1.f / (float)VV);
}

__global__ __launch_bounds__(256) void temporal_att(
    const float* __restrict__ qkt, const float* __restrict__ alphaf,
    const float* __restrict__ alphab, float* __restrict__ attt)
{
    int b = blockIdx.x;
    int slot = b & 3; int n = b >> 2;
    int dir = slot >> 1, s = slot & 1;
    int qg = (dir == 0) ? s : 2 + s;
    int kg = (dir == 0) ? 4 + s : 6 + s;
    __shared__ float qs[16][64], ks2[16][64];
    const float* base = qkt + (size_t)n * 128 * TT;
    for (int i = threadIdx.x; i < 16 * 64; i += 256) {
        int c = i >> 6, t = i & 63;
        qs [c][t] = base[(size_t)(qg * 16 + c) * TT + t];
        ks2[c][t] = base[(size_t)(kg * 16 + c) * TT + t];
    }
    __syncthreads();
    float alpha = (dir == 0) ? alphaf[s] : alphab[s];
    float* outp = attt + ((size_t)n * 4 + slot) * TT * TT;
    for (int i = threadIdx.x; i < TT * TT; i += 256) {
        int t = i >> 6, q = i & 63;
        bool keep = (dir == 0) ? (t >= q) : (q >= t);
        float d = 0.f;
        #pragma unroll
        for (int c = 0; c < 16; c++) d += qs[c][t] * ks2[c][q];
        outp[i] = keep ? tanh_fast(d * (1.f / 16.f)) * alpha : 0.f;
    }
}

// z[n, chbase+c, q, v] = sum_t tin[n,c,t,v] * att[t,q]
__global__ __launch_bounds__(256) void temporal_apply(
    const float* __restrict__ tin, const float* __restrict__ attt,
    float* __restrict__ z)
{
    int b = blockIdx.x;
    int slot = b & 3; int n = b >> 2;
    int dir = slot >> 1, s = slot & 1;
    int chbase = dir * 128 + s * 64;
    __shared__ float as[64][65];
    const float* ap = attt + ((size_t)n * 4 + slot) * TT * TT;
    for (int i = threadIdx.x; i < TT * TT; i += 256) as[i >> 6][i & 63] = ap[i];
    __syncthreads();
    const float* tb = tin + (size_t)n * CC * PP;
    float*       zb = z   + (size_t)n * 256 * PP;
    for (int r = threadIdx.x; r < CC * VV; r += 256) {
        int c = r / 25, v = r % 25;
        float acc[64];
        #pragma unroll
        for (int q = 0; q < 64; q++) acc[q] = 0.f;
        const float* tp = tb + (size_t)c * PP + v;
        for (int t = 0; t < 64; t++) {
            float a = tp[t * 25];
            #pragma unroll
            for (int q = 0; q < 64; q++) acc[q] += a * as[t][q];
        }
        float* zp = zb + (size_t)(chbase + c) * PP + v;
        #pragma unroll
        for (int q = 0; q < 64; q++) zp[q * 25] = acc[q];
    }
}

// ---------------------------------------------------------------------------
// Launcher
// ---------------------------------------------------------------------------
static float* sym(const void* symbol)
{
    void* p = nullptr;
    cudaGetSymbolAddress(&p, symbol);
    return (float*)p;
}

extern "C" void kernel_launch(void* const* d_in, const int* in_sizes, int n_in,
                              void* d_out, int out_size)
{
    const float* x       = (const float*)d_in[0];
    const float* att0s   = (const float*)d_in[1];
    const float* alphas  = (const float*)d_in[2];
    const float* W_qk_s  = (const float*)d_in[3];
    const float* b_qk_s  = (const float*)d_in[4];
    const float* W_outs  = (const float*)d_in[5];
    const float* g_outs  = (const float*)d_in[7];
    const float* be_outs = (const float*)d_in[8];
    const float* W_ffs   = (const float*)d_in[9];
    const float* g_ffs   = (const float*)d_in[11];
    const float* be_ffs  = (const float*)d_in[12];
    const float* W_qk_t  = (const float*)d_in[13];
    const float* b_qk_t  = (const float*)d_in[14];
    const float* al_f    = (const float*)d_in[15];
    const float* al_b    = (const float*)d_in[16];
    const float* W_outt  = (const float*)d_in[17];
    const float* g_outt  = (const float*)d_in[19];
    const float* be_outt = (const float*)d_in[20];
    const float* W_fft   = (const float*)d_in[21];
    const float* g_fft   = (const float*)d_in[23];
    const float* be_fft  = (const float*)d_in[24];
    const float* W_tcn   = (const float*)d_in[25];
    const float* g_tcn   = (const float*)d_in[27];
    const float* be_tcn  = (const float*)d_in[28];
    float* out = (float*)d_out;

    float* p_qk   = sym(g_qk);
    float* p_y    = sym(g_y);
    float* p_conv = sym(g_conv);
    float* p_sout = sym(g_sout);
    float* p_b1   = sym(g_b1);
    float* p_b2   = sym(g_b2);
    float* p_xbar = sym(g_xbar);
    float* p_qkt  = sym(g_qkt);
    float* p_attt = sym(g_attt);
    float* p_z    = sym(g_z);
    float* p_st   = sym(g_stats);

    const size_t TOT = (size_t)NB * CC * PP;
    const int EW_BLOCKS4 = (int)((TOT / 4 + 255) / 256);
    const dim3 G13(13, 1, NB);

    zero_stats_kernel<<<3, 256>>>(p_st);

    // --- spatial attention (fused att + apply) ---
    sgemm_tf32<0><<<dim3(13, 2, NB), 256>>>(x, W_qk_s, b_qk_s, p_qk, 64, 96, nullptr);
    spatial_fused<<<NB * TT, 256>>>(x, p_qk, att0s, alphas, p_y);

    // y = BN(conv(y, W_outs)); y = leaky(x + y)   [bias cancels in BN]
    sgemm_tf32<0><<<G13, 256>>>(p_y, W_outs, nullptr, p_conv, 192, 64, p_st + 0);
    bn_apply<<<EW_BLOCKS4, 256>>>((const float4*)p_conv, (const float4*)x,
                                  g_outs, be_outs, p_st + 0, (float4*)p_b1);

    // y = BN(conv(y, W_ffs)); s_out = leaky(x + y)
    sgemm_tf32<0><<<G13, 256>>>(p_b1, W_ffs, nullptr, p_conv, 64, 64, p_st + 128);
    bn_apply<<<EW_BLOCKS4, 256>>>((const float4*)p_conv, (const float4*)x,
                                  g_ffs, be_ffs, p_st + 128, (float4*)p_sout);

    // --- temporal attention ---
    mean_v_kernel<<<(NB * CC * TT + 255) / 256, 256>>>(p_sout, p_xbar);
    sgemm_small<<<dim3(1, 2, NB), 256>>>(p_xbar, W_qk_t, b_qk_t, p_qkt, 64, 128, TT);
    temporal_att<<<NB * 4, 256>>>(p_qkt, al_f, al_b, p_attt);
    temporal_apply<<<NB * 4, 256>>>(p_sout, p_attt, p_z);

    // z = BN(conv(z, W_outt)); z = leaky(t_in + z)
    sgemm_tf32<0><<<G13, 256>>>(p_z, W_outt, nullptr, p_conv, 256, 64, p_st + 256);
    bn_apply<<<EW_BLOCKS4, 256>>>((const float4*)p_conv, (const float4*)p_sout,
                                  g_outt, be_outt, p_st + 256, (float4*)p_b1);

    // z = BN(conv(z, W_fft)); z = leaky(t_in + z)
    sgemm_tf32<0><<<G13, 256>>>(p_b1, W_fft, nullptr, p_conv, 64, 64, p_st + 384);
    bn_apply<<<EW_BLOCKS4, 256>>>((const float4*)p_conv, (const float4*)p_sout,
                                  g_fft, be_fft, p_st + 384, (float4*)p_b2);

    // --- TCN as K=448 GEMM (k = c*7+dt, shifted B rows) ---
    sgemm_tf32<1><<<G13, 256>>>(p_b2, W_tcn, nullptr, p_conv, 448, 64, p_st + 512);
    bn_apply<<<EW_BLOCKS4, 256>>>((const float4*)p_conv, (const float4*)p_b2,
                                  g_tcn, be_tcn, p_st + 512, (float4*)out);
}

// round 14
// speedup vs baseline: 1.2724x; 1.2488x over previous
#include <cuda_runtime.h>
#include <cuda_bf16.h>
#include <math.h>
#include <cstdint>

// ---------------------------------------------------------------------------
// Problem constants
// ---------------------------------------------------------------------------
#define NB   128          // batch N
#define CC   64           // channels C = O
#define TT   64           // T
#define VV   25           // V
#define PP   (TT*VV)      // 1600 positions per (n, channel)
#define SS   3            // spatial heads
#define NTV  (NB*TT*VV)   // 204800 samples per channel for BN

// ---------------------------------------------------------------------------
// Scratch (device globals; no allocation allowed)
// ---------------------------------------------------------------------------
__device__ float g_qk  [ (size_t)NB*96*PP ];        // spatial qk conv out
__device__ float g_y   [ (size_t)NB*192*PP ];       // spatial attended
__device__ float g_conv[ (size_t)NB*CC*PP ];        // generic conv output
__device__ float g_sout[ (size_t)NB*CC*PP ];        // s_out == t_in
__device__ float g_b1  [ (size_t)NB*CC*PP ];
__device__ float g_b2  [ (size_t)NB*CC*PP ];
__device__ float g_xbar[ (size_t)NB*CC*TT ];        // mean over V
__device__ float g_qkt [ (size_t)NB*128*TT ];
__device__ float g_attt[ (size_t)NB*4*TT*TT ];      // 4 slots: f0,f1,b0,b1
__device__ float g_z   [ (size_t)NB*256*PP ];       // temporal attended
__device__ float g_stats[5*128];                    // 5 BNs x (sum[64], sumsq[64])

// ---------------------------------------------------------------------------
// cp.async helpers
// ---------------------------------------------------------------------------
__device__ __forceinline__ unsigned int smem_u32(const void* p)
{
    return (unsigned int)__cvta_generic_to_shared(p);
}
__device__ __forceinline__ void cp16(unsigned int dst, const void* src, int sbytes)
{
    asm volatile("cp.async.cg.shared.global [%0], [%1], 16, %2;"
                 :: "r"(dst), "l"(src), "r"(sbytes));
}
__device__ __forceinline__ void cp4(unsigned int dst, const void* src, int sbytes)
{
    asm volatile("cp.async.ca.shared.global [%0], [%1], 4, %2;"
                 :: "r"(dst), "l"(src), "r"(sbytes));
}
__device__ __forceinline__ void cp_commit()
{
    asm volatile("cp.async.commit_group;");
}
template<int N>
__device__ __forceinline__ void cp_wait()
{
    asm volatile("cp.async.wait_group %0;" :: "n"(N));
}

// ---------------------------------------------------------------------------
// tf32 helpers (3xTF32 error-compensated path)
// ---------------------------------------------------------------------------
__device__ __forceinline__ void split_tf32(float x, unsigned& hi, unsigned& lo)
{
    asm("cvt.rna.tf32.f32 %0, %1;" : "=r"(hi) : "f"(x));
    float r = x - __uint_as_float(hi);
    asm("cvt.rna.tf32.f32 %0, %1;" : "=r"(lo) : "f"(r));
}
__device__ __forceinline__ void mma_tf32(float* c, const unsigned* a,
                                         unsigned b0, unsigned b1)
{
    asm volatile(
        "mma.sync.aligned.m16n8k8.row.col.f32.tf32.tf32.f32 "
        "{%0,%1,%2,%3}, {%4,%5,%6,%7}, {%8,%9}, {%0,%1,%2,%3};"
        : "+f"(c[0]), "+f"(c[1]), "+f"(c[2]), "+f"(c[3])
        : "r"(a[0]), "r"(a[1]), "r"(a[2]), "r"(a[3]), "r"(b0), "r"(b1));
}
__device__ __forceinline__ float tanh_fast(float x)
{
    float y;
    asm("tanh.approx.f32 %0, %1;" : "=f"(y) : "f"(x));
    return y;
}

// ---------------------------------------------------------------------------
// Tensor-core GEMM (3xTF32) for 1x1 convs and the TCN-as-GEMM.
// (unchanged from the 2060us baseline)
// ---------------------------------------------------------------------------
template<int TCN>
__global__ __launch_bounds__(256, 2) void sgemm_tf32(
    const float* __restrict__ X, const float* __restrict__ W,
    const float* __restrict__ bias, float* __restrict__ Y,
    int CIN, int COUT, float* __restrict__ stats)
{
    const int P  = PP;
    const int n  = blockIdx.z;
    const int m0 = blockIdx.y * 64;
    const int p0 = blockIdx.x * 128;
    const float* Xn = X + (size_t)n * (TCN ? 64 : CIN) * P;
    float*       Yn = Y + (size_t)n * COUT * P;

    __shared__ __align__(16) float As[2][64][20];
    __shared__ __align__(16) float Bs[2][16][132];

    float acc[2][4][4];
    #pragma unroll
    for (int i = 0; i < 2; i++)
        #pragma unroll
        for (int j = 0; j < 4; j++)
            #pragma unroll
            for (int c = 0; c < 4; c++) acc[i][j][c] = 0.f;

    const int lane = threadIdx.x & 31;
    const int warp = threadIdx.x >> 5;
    const int g    = lane >> 2;
    const int t4   = lane & 3;
    const int wm   = warp >> 2;
    const int wn   = warp & 3;

    const int nk = CIN / 16;
    float pa[4];

    auto issueB = [&](int kt, int buf) {
        const int k0 = kt * 16;
        if (!TCN) {
            #pragma unroll
            for (int i = 0; i < 2; i++) {
                int f = threadIdx.x + i * 256;
                int k = f >> 5, p = (f & 31) * 4;
                bool ok = (p0 + p) < P;
                const float* src = ok ? &Xn[(size_t)(k0 + k) * P + p0 + p] : Xn;
                cp16(smem_u32(&Bs[buf][k][p]), src, ok ? 16 : 0);
            }
        } else {
            #pragma unroll
            for (int i = 0; i < 8; i++) {
                int idx = threadIdx.x + i * 256;
                int k = idx >> 7, p = idx & 127;
                int kk = k0 + k;
                int c = kk / 7, dt = kk % 7;
                int src = p0 + p + (dt - 3) * 25;
                bool ok = (p0 + p) < P && src >= 0 && src < P;
                const float* sp = ok ? &Xn[(size_t)c * P + src] : Xn;
                cp4(smem_u32(&Bs[buf][k][p]), sp, ok ? 4 : 0);
            }
        }
        cp_commit();
    };

    #pragma unroll
    for (int i = 0; i < 4; i++) {
        int idx = threadIdx.x + i * 256;
        int m = idx >> 4, k = idx & 15;
        float w = 0.f;
        if (m0 + m < COUT) w = W[(size_t)(m0 + m) * CIN + k];
        As[0][m][k] = w;
    }
    issueB(0, 0);

    for (int it = 0; it < nk; it++) {
        const int cur = it & 1;
        const int nxt = 1 - cur;
        const bool more = (it + 1 < nk);

        if (more) {
            issueB(it + 1, nxt);
            const int k0n = (it + 1) * 16;
            #pragma unroll
            for (int i = 0; i < 4; i++) {
                int idx = threadIdx.x + i * 256;
                int m = idx >> 4, k = idx & 15;
                float w = 0.f;
                if (m0 + m < COUT) w = W[(size_t)(m0 + m) * CIN + k0n + k];
                pa[i] = w;
            }
        }

        if (more) cp_wait<1>(); else cp_wait<0>();
        __syncthreads();

        #pragma unroll
        for (int ks = 0; ks < 2; ks++) {
            const int kk = ks * 8;
            unsigned ahi[2][4], alo[2][4];
            #pragma unroll
            for (int mf = 0; mf < 2; mf++) {
                int r = wm * 32 + mf * 16 + g;
                float a0 = As[cur][r    ][kk + t4];
                float a1 = As[cur][r + 8][kk + t4];
                float a2 = As[cur][r    ][kk + t4 + 4];
                float a3 = As[cur][r + 8][kk + t4 + 4];
                split_tf32(a0, ahi[mf][0], alo[mf][0]);
                split_tf32(a1, ahi[mf][1], alo[mf][1]);
                split_tf32(a2, ahi[mf][2], alo[mf][2]);
                split_tf32(a3, ahi[mf][3], alo[mf][3]);
            }
            #pragma unroll
            for (int nf = 0; nf < 4; nf++) {
                int col = wn * 32 + nf * 8 + g;
                float b0 = Bs[cur][kk + t4    ][col];
                float b1 = Bs[cur][kk + t4 + 4][col];
                unsigned bh0, bl0, bh1, bl1;
                split_tf32(b0, bh0, bl0);
                split_tf32(b1, bh1, bl1);
                #pragma unroll
                for (int mf = 0; mf < 2; mf++) {
                    mma_tf32(acc[mf][nf], ahi[mf], bh0, bh1);
                    mma_tf32(acc[mf][nf], ahi[mf], bl0, bl1);
                    mma_tf32(acc[mf][nf], alo[mf], bh0, bh1);
                }
            }
        }

        if (more) {
            #pragma unroll
            for (int i = 0; i < 4; i++) {
                int idx = threadIdx.x + i * 256;
                int m = idx >> 4, k = idx & 15;
                As[nxt][m][k] = pa[i];
            }
        }
        __syncthreads();
    }

    #pragma unroll
    for (int mf = 0; mf < 2; mf++) {
        #pragma unroll
        for (int half = 0; half < 2; half++) {
            int m = m0 + wm * 32 + mf * 16 + g + half * 8;
            if (m < COUT) {
                float bv = bias ? bias[m] : 0.f;
                #pragma unroll
                for (int nf = 0; nf < 4; nf++) {
                    int p = p0 + wn * 32 + nf * 8 + 2 * t4;
                    if (p < P) {
                        float2 v;
                        v.x = acc[mf][nf][half * 2 + 0] + bv;
                        v.y = acc[mf][nf][half * 2 + 1] + bv;
                        *(float2*)&Yn[(size_t)m * P + p] = v;
                    }
                }
            }
        }
    }
    if (stats) {
        #pragma unroll
        for (int mf = 0; mf < 2; mf++) {
            #pragma unroll
            for (int half = 0; half < 2; half++) {
                int m = m0 + wm * 32 + mf * 16 + g + half * 8;
                float s = 0.f, s2 = 0.f;
                #pragma unroll
                for (int nf = 0; nf < 4; nf++) {
                    float v0 = acc[mf][nf][half * 2 + 0];
                    float v1 = acc[mf][nf][half * 2 + 1];
                    s  += v0 + v1;
                    s2 += v0 * v0 + v1 * v1;
                }
                s  += __shfl_down_sync(0xffffffffu, s,  1, 4);
                s  += __shfl_down_sync(0xffffffffu, s,  2, 4);
                s2 += __shfl_down_sync(0xffffffffu, s2, 1, 4);
                s2 += __shfl_down_sync(0xffffffffu, s2, 2, 4);
                if (t4 == 0 && m < COUT) {
                    atomicAdd(&stats[m], s);
                    atomicAdd(&stats[64 + m], s2);
                }
            }
        }
    }
}

// ---------------------------------------------------------------------------
// Small GEMM for qk_t (P=64 columns only).
// ---------------------------------------------------------------------------
__global__ __launch_bounds__(256) void sgemm_small(
    const float* __restrict__ X, const float* __restrict__ W,
    const float* __restrict__ bias, float* __restrict__ Y,
    int CIN, int COUT, int P)
{
    const int n  = blockIdx.z;
    const int m0 = blockIdx.y * 64;
    const float* Xn = X + (size_t)n * CIN * P;
    float*       Yn = Y + (size_t)n * COUT * P;

    __shared__ float As[16][68];
    __shared__ float Bs[16][68];
    float acc[4][4];
    #pragma unroll
    for (int i = 0; i < 4; i++)
        #pragma unroll
        for (int j = 0; j < 4; j++) acc[i][j] = 0.f;

    const int tx = threadIdx.x & 15;
    const int ty = threadIdx.x >> 4;

    for (int k0 = 0; k0 < CIN; k0 += 16) {
        for (int i = threadIdx.x; i < 64 * 16; i += 256) {
            int m = i >> 4, k = i & 15;
            float w = 0.f;
            if (m0 + m < COUT) w = W[(size_t)(m0 + m) * CIN + k0 + k];
            As[k][m] = w;
        }
        for (int i = threadIdx.x; i < 16 * 64; i += 256) {
            int k = i >> 6, p = i & 63;
            Bs[k][p] = (p < P) ? Xn[(size_t)(k0 + k) * P + p] : 0.f;
        }
        __syncthreads();
        #pragma unroll
        for (int k = 0; k < 16; k++) {
            float a[4], b[4];
            #pragma unroll
            for (int i = 0; i < 4; i++) a[i] = As[k][ty * 4 + i];
            #pragma unroll
            for (int j = 0; j < 4; j++) b[j] = Bs[k][tx * 4 + j];
            #pragma unroll
            for (int i = 0; i < 4; i++)
                #pragma unroll
                for (int j = 0; j < 4; j++) acc[i][j] += a[i] * b[j];
        }
        __syncthreads();
    }
    #pragma unroll
    for (int i = 0; i < 4; i++) {
        int m = m0 + ty * 4 + i;
        if (m < COUT) {
            float bv = bias ? bias[m] : 0.f;
            #pragma unroll
            for (int j = 0; j < 4; j++) {
                int p = tx * 4 + j;
                if (p < P) Yn[(size_t)m * P + p] = acc[i][j] + bv;
            }
        }
    }
}

// ---------------------------------------------------------------------------
// Fused spatial attention + apply: one block per (n,t).
// Apply-phase xs reads vectorized to LDS.128 (cg*4 is 16B-aligned).
// ---------------------------------------------------------------------------
__global__ __launch_bounds__(256) void spatial_fused(
    const float* __restrict__ x, const float* __restrict__ qk,
    const float* __restrict__ att0, const float* __restrict__ alphas,
    float* __restrict__ y)
{
    int b = blockIdx.x;
    int t = b % TT; int n = b / TT;
    __shared__ float qs[3][16][25];
    __shared__ float ks[3][16][25];
    __shared__ __align__(16) float xs[25][68];    // [u][c], rows 16B-aligned
    __shared__ float as[3][25][26];               // [s][u][v]

    const float* base = qk + (size_t)n * 96 * PP + t * VV;
    for (int i = threadIdx.x; i < 48 * 25; i += 256) {
        int c = i / 25, u = i % 25;
        qs[c >> 4][c & 15][u] = base[(size_t)c * PP + u];
        ks[c >> 4][c & 15][u] = base[(size_t)(48 + c) * PP + u];
    }
    const float* xb = x + (size_t)n * CC * PP + t * VV;
    for (int i = threadIdx.x; i < 64 * 25; i += 256) {
        int c = i / 25, u = i % 25;
        xs[u][c] = xb[(size_t)c * PP + u];
    }
    __syncthreads();

    for (int i = threadIdx.x; i < 3 * 625; i += 256) {
        int s = i / 625, r = i % 625;
        int u = r / 25, v = r % 25;
        float d = 0.f;
        #pragma unroll
        for (int c = 0; c < 16; c++) d += qs[s][c][u] * ks[s][c][v];
        as[s][u][v] = att0[(size_t)s * 625 + r] + tanh_fast(d * (1.f / 16.f)) * alphas[s];
    }
    __syncthreads();

    if (threadIdx.x >= 240) return;
    int s  = threadIdx.x / 80;
    int r  = threadIdx.x % 80;
    int cg = r / 5;
    int vg = r % 5;
    float acc[4][5];
    #pragma unroll
    for (int i = 0; i < 4; i++)
        #pragma unroll
        for (int j = 0; j < 5; j++) acc[i][j] = 0.f;
    #pragma unroll
    for (int u = 0; u < 25; u++) {
        float a[4], bb[5];
        *(float4*)a = *(const float4*)&xs[u][cg * 4];   // one LDS.128
        #pragma unroll
        for (int j = 0; j < 5; j++) bb[j] = as[s][u][vg * 5 + j];
        #pragma unroll
        for (int i = 0; i < 4; i++)
            #pragma unroll
            for (int j = 0; j < 5; j++) acc[i][j] += a[i] * bb[j];
    }
    float* yb = y + (size_t)n * 192 * PP + t * VV;
    #pragma unroll
    for (int i = 0; i < 4; i++) {
        float* yp = yb + (size_t)(s * 64 + cg * 4 + i) * PP + vg * 5;
        #pragma unroll
        for (int j = 0; j < 5; j++) yp[j] = acc[i][j];
    }
}

__global__ void zero_stats_kernel(float* s)
{
    int i = blockIdx.x * blockDim.x + threadIdx.x;
    if (i < 5 * 128) s[i] = 0.f;
}

// out = leaky( res + gamma_c*(conv-mu_c)*rsqrt(var_c+eps) + beta_c ), float4
__global__ __launch_bounds__(256) void bn_apply(
    const float4* __restrict__ conv, const float4* __restrict__ res,
    const float* __restrict__ gamma, const float* __restrict__ beta,
    const float* __restrict__ stats, float4* __restrict__ out)
{
    size_t i = (size_t)blockIdx.x * blockDim.x + threadIdx.x;
    const size_t TOT4 = (size_t)NB * CC * PP / 4;
    if (i >= TOT4) return;
    int c = (int)((i / (PP / 4)) & 63);
    float mu  = stats[c] * (1.f / (float)NTV);
    float var = stats[64 + c] * (1.f / (float)NTV) - mu * mu;
    float g = gamma[c] * rsqrtf(var + 1e-5f);
    float sh = beta[c] - mu * g;
    float4 cv = conv[i], rv = res[i], o;
    float v;
    v = rv.x + cv.x * g + sh; o.x = v > 0.f ? v : 0.1f * v;
    v = rv.y + cv.y * g + sh; o.y = v > 0.f ? v : 0.1f * v;
    v = rv.z + cv.z * g + sh; o.z = v > 0.f ? v : 0.1f * v;
    v = rv.w + cv.w * g + sh; o.w = v > 0.f ? v : 0.1f * v;
    out[i] = o;
}

// ---------------------------------------------------------------------------
// Temporal path
// ---------------------------------------------------------------------------
__global__ void mean_v_kernel(const float* __restrict__ X, float* __restrict__ xb)
{
    int i = blockIdx.x * blockDim.x + threadIdx.x;  // over N*C*T
    if (i >= NB * CC * TT) return;
    const float* p = X + (size_t)i * VV;
    float s = 0.f;
    #pragma unroll
    for (int v = 0; v < VV; v++) s += p[v];
    xb[i] = s * (1.f / (float)VV);
}

__global__ __launch_bounds__(256) void temporal_att(
    const float* __restrict__ qkt, const float* __restrict__ alphaf,
    const float* __restrict__ alphab, float* __restrict__ attt)
{
    int b = blockIdx.x;
    int slot = b & 3; int n = b >> 2;
    int dir = slot >> 1, s = slot & 1;
    int qg = (dir == 0) ? s : 2 + s;
    int kg = (dir == 0) ? 4 + s : 6 + s;
    __shared__ float qs[16][64], ks2[16][64];
    const float* base = qkt + (size_t)n * 128 * TT;
    for (int i = threadIdx.x; i < 16 * 64; i += 256) {
        int c = i >> 6, t = i & 63;
        qs [c][t] = base[(size_t)(qg * 16 + c) * TT + t];
        ks2[c][t] = base[(size_t)(kg * 16 + c) * TT + t];
    }
    __syncthreads();
    float alpha = (dir == 0) ? alphaf[s] : alphab[s];
    float* outp = attt + ((size_t)n * 4 + slot) * TT * TT;
    for (int i = threadIdx.x; i < TT * TT; i += 256) {
        int t = i >> 6, q = i & 63;
        bool keep = (dir == 0) ? (t >= q) : (q >= t);
        float d = 0.f;
        #pragma unroll
        for (int c = 0; c < 16; c++) d += qs[c][t] * ks2[c][q];
        outp[i] = keep ? tanh_fast(d * (1.f / 16.f)) * alpha : 0.f;
    }
}

// z[n, chbase+c, q, v] = sum_t tin[n,c,t,v] * att[t,q]
// as padded to 68 floats/row (16B-aligned); inner q reads via uniform
// LDS.128 broadcasts (16 per t instead of 64 scalar LDS).
__global__ __launch_bounds__(256) void temporal_apply(
    const float* __restrict__ tin, const float* __restrict__ attt,
    float* __restrict__ z)
{
    int b = blockIdx.x;
    int slot = b & 3; int n = b >> 2;
    int dir = slot >> 1, s = slot & 1;
    int chbase = dir * 128 + s * 64;
    __shared__ __align__(16) float as[64][68];
    const float* ap = attt + ((size_t)n * 4 + slot) * TT * TT;
    for (int i = threadIdx.x; i < TT * TT; i += 256) as[i >> 6][i & 63] = ap[i];
    __syncthreads();
    const float* tb = tin + (size_t)n * CC * PP;
    float*       zb = z   + (size_t)n * 256 * PP;
    for (int r = threadIdx.x; r < CC * VV; r += 256) {
        int c = r / 25, v = r % 25;
        float acc[64];
        #pragma unroll
        for (int q = 0; q < 64; q++) acc[q] = 0.f;
        const float* tp = tb + (size_t)c * PP + v;
        for (int t = 0; t < 64; t++) {
            float a = tp[t * 25];
            #pragma unroll
            for (int q4 = 0; q4 < 16; q4++) {
                float4 w = *(const float4*)&as[t][q4 * 4];  // uniform broadcast
                acc[q4 * 4 + 0] += a * w.x;
                acc[q4 * 4 + 1] += a * w.y;
                acc[q4 * 4 + 2] += a * w.z;
                acc[q4 * 4 + 3] += a * w.w;
            }
        }
        float* zp = zb + (size_t)(chbase + c) * PP + v;
        #pragma unroll
        for (int q = 0; q < 64; q++) zp[q * 25] = acc[q];
    }
}

// ---------------------------------------------------------------------------
// Launcher
// ---------------------------------------------------------------------------
static float* sym(const void* symbol)
{
    void* p = nullptr;
    cudaGetSymbolAddress(&p, symbol);
    return (float*)p;
}

extern "C" void kernel_launch(void* const* d_in, const int* in_sizes, int n_in,
                              void* d_out, int out_size)
{
    const float* x       = (const float*)d_in[0];
    const float* att0s   = (const float*)d_in[1];
    const float* alphas  = (const float*)d_in[2];
    const float* W_qk_s  = (const float*)d_in[3];
    const float* b_qk_s  = (const float*)d_in[4];
    const float* W_outs  = (const float*)d_in[5];
    const float* g_outs  = (const float*)d_in[7];
    const float* be_outs = (const float*)d_in[8];
    const float* W_ffs   = (const float*)d_in[9];
    const float* g_ffs   = (const float*)d_in[11];
    const float* be_ffs  = (const float*)d_in[12];
    const float* W_qk_t  = (const float*)d_in[13];
    const float* b_qk_t  = (const float*)d_in[14];
    const float* al_f    = (const float*)d_in[15];
    const float* al_b    = (const float*)d_in[16];
    const float* W_outt  = (const float*)d_in[17];
    const float* g_outt  = (const float*)d_in[19];
    const float* be_outt = (const float*)d_in[20];
    const float* W_fft   = (const float*)d_in[21];
    const float* g_fft   = (const float*)d_in[23];
    const float* be_fft  = (const float*)d_in[24];
    const float* W_tcn   = (const float*)d_in[25];
    const float* g_tcn   = (const float*)d_in[27];
    const float* be_tcn  = (const float*)d_in[28];
    float* out = (float*)d_out;

    float* p_qk   = sym(g_qk);
    float* p_y    = sym(g_y);
    float* p_conv = sym(g_conv);
    float* p_sout = sym(g_sout);
    float* p_b1   = sym(g_b1);
    float* p_b2   = sym(g_b2);
    float* p_xbar = sym(g_xbar);
    float* p_qkt  = sym(g_qkt);
    float* p_attt = sym(g_attt);
    float* p_z    = sym(g_z);
    float* p_st   = sym(g_stats);

    const size_t TOT = (size_t)NB * CC * PP;
    const int EW_BLOCKS4 = (int)((TOT / 4 + 255) / 256);
    const dim3 G13(13, 1, NB);

    zero_stats_kernel<<<3, 256>>>(p_st);

    // --- spatial attention (fused att + apply) ---
    sgemm_tf32<0><<<dim3(13, 2, NB), 256>>>(x, W_qk_s, b_qk_s, p_qk, 64, 96, nullptr);
    spatial_fused<<<NB * TT, 256>>>(x, p_qk, att0s, alphas, p_y);

    // y = BN(conv(y, W_outs)); y = leaky(x + y)   [bias cancels in BN]
    sgemm_tf32<0><<<G13, 256>>>(p_y, W_outs, nullptr, p_conv, 192, 64, p_st + 0);
    bn_apply<<<EW_BLOCKS4, 256>>>((const float4*)p_conv, (const float4*)x,
                                  g_outs, be_outs, p_st + 0, (float4*)p_b1);

    // y = BN(conv(y, W_ffs)); s_out = leaky(x + y)
    sgemm_tf32<0><<<G13, 256>>>(p_b1, W_ffs, nullptr, p_conv, 64, 64, p_st + 128);
    bn_apply<<<EW_BLOCKS4, 256>>>((const float4*)p_conv, (const float4*)x,
                                  g_ffs, be_ffs, p_st + 128, (float4*)p_sout);

    // --- temporal attention ---
    mean_v_kernel<<<(NB * CC * TT + 255) / 256, 256>>>(p_sout, p_xbar);
    sgemm_small<<<dim3(1, 2, NB), 256>>>(p_xbar, W_qk_t, b_qk_t, p_qkt, 64, 128, TT);
    temporal_att<<<NB * 4, 256>>>(p_qkt, al_f, al_b, p_attt);
    temporal_apply<<<NB * 4, 256>>>(p_sout, p_attt, p_z);

    // z = BN(conv(z, W_outt)); z = leaky(t_in + z)
    sgemm_tf32<0><<<G13, 256>>>(p_z, W_outt, nullptr, p_conv, 256, 64, p_st + 256);
    bn_apply<<<EW_BLOCKS4, 256>>>((const float4*)p_conv, (const float4*)p_sout,
                                  g_outt, be_outt, p_st + 256, (float4*)p_b1);

    // z = BN(conv(z, W_fft)); z = leaky(t_in + z)
    sgemm_tf32<0><<<G13, 256>>>(p_b1, W_fft, nullptr, p_conv, 64, 64, p_st + 384);
    bn_apply<<<EW_BLOCKS4, 256>>>((const float4*)p_conv, (const float4*)p_sout,
                                  g_fft, be_fft, p_st + 384, (float4*)p_b2);

    // --- TCN as K=448 GEMM (k = c*7+dt, shifted B rows) ---
    sgemm_tf32<1><<<G13, 256>>>(p_b2, W_tcn, nullptr, p_conv, 448, 64, p_st + 512);
    bn_apply<<<EW_BLOCKS4, 256>>>((const float4*)p_conv, (const float4*)p_b2,
                                  g_tcn, be_tcn, p_st + 512, (float4*)out);
}

// round 15
// speedup vs baseline: 1.3247x; 1.0411x over previous
#include <cuda_runtime.h>
#include <cuda_bf16.h>
#include <math.h>
#include <cstdint>

// ---------------------------------------------------------------------------
// Problem constants
// ---------------------------------------------------------------------------
#define NB   128          // batch N
#define CC   64           // channels C = O
#define TT   64           // T
#define VV   25           // V
#define PP   (TT*VV)      // 1600 positions per (n, channel)
#define SS   3            // spatial heads
#define NTV  (NB*TT*VV)   // 204800 samples per channel for BN

// ---------------------------------------------------------------------------
// Scratch (device globals; no allocation allowed)
// ---------------------------------------------------------------------------
__device__ float g_qk  [ (size_t)NB*96*PP ];        // spatial qk conv out
__device__ float g_y   [ (size_t)NB*192*PP ];       // spatial attended
__device__ float g_conv[ (size_t)NB*CC*PP ];        // generic conv output
__device__ float g_sout[ (size_t)NB*CC*PP ];        // s_out == t_in
__device__ float g_b1  [ (size_t)NB*CC*PP ];
__device__ float g_b2  [ (size_t)NB*CC*PP ];
__device__ float g_xbar[ (size_t)NB*CC*TT ];        // mean over V
__device__ float g_qkt [ (size_t)NB*128*TT ];
__device__ float g_attt[ (size_t)NB*4*TT*TT ];      // 4 slots: f0,f1,b0,b1
__device__ float g_z   [ (size_t)NB*256*PP ];       // temporal attended
__device__ float g_stats[5*128];                    // 5 BNs x (sum[64], sumsq[64])

// ---------------------------------------------------------------------------
// cp.async helpers
// ---------------------------------------------------------------------------
__device__ __forceinline__ unsigned int smem_u32(const void* p)
{
    return (unsigned int)__cvta_generic_to_shared(p);
}
__device__ __forceinline__ void cp16(unsigned int dst, const void* src, int sbytes)
{
    asm volatile("cp.async.cg.shared.global [%0], [%1], 16, %2;"
                 :: "r"(dst), "l"(src), "r"(sbytes));
}
__device__ __forceinline__ void cp4(unsigned int dst, const void* src, int sbytes)
{
    asm volatile("cp.async.ca.shared.global [%0], [%1], 4, %2;"
                 :: "r"(dst), "l"(src), "r"(sbytes));
}
__device__ __forceinline__ void cp_commit()
{
    asm volatile("cp.async.commit_group;");
}
template<int N>
__device__ __forceinline__ void cp_wait()
{
    asm volatile("cp.async.wait_group %0;" :: "n"(N));
}

// ---------------------------------------------------------------------------
// tf32 helpers (3xTF32 error-compensated path)
// ---------------------------------------------------------------------------
__device__ __forceinline__ void split_tf32(float x, unsigned& hi, unsigned& lo)
{
    asm("cvt.rna.tf32.f32 %0, %1;" : "=r"(hi) : "f"(x));
    float r = x - __uint_as_float(hi);
    asm("cvt.rna.tf32.f32 %0, %1;" : "=r"(lo) : "f"(r));
}
__device__ __forceinline__ void mma_tf32(float* c, const unsigned* a,
                                         unsigned b0, unsigned b1)
{
    asm volatile(
        "mma.sync.aligned.m16n8k8.row.col.f32.tf32.tf32.f32 "
        "{%0,%1,%2,%3}, {%4,%5,%6,%7}, {%8,%9}, {%0,%1,%2,%3};"
        : "+f"(c[0]), "+f"(c[1]), "+f"(c[2]), "+f"(c[3])
        : "r"(a[0]), "r"(a[1]), "r"(a[2]), "r"(a[3]), "r"(b0), "r"(b1));
}
__device__ __forceinline__ float tanh_fast(float x)
{
    float y;
    asm("tanh.approx.f32 %0, %1;" : "=f"(y) : "f"(x));
    return y;
}

// ---------------------------------------------------------------------------
// Tensor-core GEMM (3xTF32) for 1x1 convs and the TCN-as-GEMM.
// (unchanged from the 1655us baseline)
// ---------------------------------------------------------------------------
template<int TCN>
__global__ __launch_bounds__(256, 2) void sgemm_tf32(
    const float* __restrict__ X, const float* __restrict__ W,
    const float* __restrict__ bias, float* __restrict__ Y,
    int CIN, int COUT, float* __restrict__ stats)
{
    const int P  = PP;
    const int n  = blockIdx.z;
    const int m0 = blockIdx.y * 64;
    const int p0 = blockIdx.x * 128;
    const float* Xn = X + (size_t)n * (TCN ? 64 : CIN) * P;
    float*       Yn = Y + (size_t)n * COUT * P;

    __shared__ __align__(16) float As[2][64][20];
    __shared__ __align__(16) float Bs[2][16][132];

    float acc[2][4][4];
    #pragma unroll
    for (int i = 0; i < 2; i++)
        #pragma unroll
        for (int j = 0; j < 4; j++)
            #pragma unroll
            for (int c = 0; c < 4; c++) acc[i][j][c] = 0.f;

    const int lane = threadIdx.x & 31;
    const int warp = threadIdx.x >> 5;
    const int g    = lane >> 2;
    const int t4   = lane & 3;
    const int wm   = warp >> 2;
    const int wn   = warp & 3;

    const int nk = CIN / 16;
    float pa[4];

    auto issueB = [&](int kt, int buf) {
        const int k0 = kt * 16;
        if (!TCN) {
            #pragma unroll
            for (int i = 0; i < 2; i++) {
                int f = threadIdx.x + i * 256;
                int k = f >> 5, p = (f & 31) * 4;
                bool ok = (p0 + p) < P;
                const float* src = ok ? &Xn[(size_t)(k0 + k) * P + p0 + p] : Xn;
                cp16(smem_u32(&Bs[buf][k][p]), src, ok ? 16 : 0);
            }
        } else {
            #pragma unroll
            for (int i = 0; i < 8; i++) {
                int idx = threadIdx.x + i * 256;
                int k = idx >> 7, p = idx & 127;
                int kk = k0 + k;
                int c = kk / 7, dt = kk % 7;
                int src = p0 + p + (dt - 3) * 25;
                bool ok = (p0 + p) < P && src >= 0 && src < P;
                const float* sp = ok ? &Xn[(size_t)c * P + src] : Xn;
                cp4(smem_u32(&Bs[buf][k][p]), sp, ok ? 4 : 0);
            }
        }
        cp_commit();
    };

    #pragma unroll
    for (int i = 0; i < 4; i++) {
        int idx = threadIdx.x + i * 256;
        int m = idx >> 4, k = idx & 15;
        float w = 0.f;
        if (m0 + m < COUT) w = W[(size_t)(m0 + m) * CIN + k];
        As[0][m][k] = w;
    }
    issueB(0, 0);

    for (int it = 0; it < nk; it++) {
        const int cur = it & 1;
        const int nxt = 1 - cur;
        const bool more = (it + 1 < nk);

        if (more) {
            issueB(it + 1, nxt);
            const int k0n = (it + 1) * 16;
            #pragma unroll
            for (int i = 0; i < 4; i++) {
                int idx = threadIdx.x + i * 256;
                int m = idx >> 4, k = idx & 15;
                float w = 0.f;
                if (m0 + m < COUT) w = W[(size_t)(m0 + m) * CIN + k0n + k];
                pa[i] = w;
            }
        }

        if (more) cp_wait<1>(); else cp_wait<0>();
        __syncthreads();

        #pragma unroll
        for (int ks = 0; ks < 2; ks++) {
            const int kk = ks * 8;
            unsigned ahi[2][4], alo[2][4];
            #pragma unroll
            for (int mf = 0; mf < 2; mf++) {
                int r = wm * 32 + mf * 16 + g;
                float a0 = As[cur][r    ][kk + t4];
                float a1 = As[cur][r + 8][kk + t4];
                float a2 = As[cur][r    ][kk + t4 + 4];
                float a3 = As[cur][r + 8][kk + t4 + 4];
                split_tf32(a0, ahi[mf][0], alo[mf][0]);
                split_tf32(a1, ahi[mf][1], alo[mf][1]);
                split_tf32(a2, ahi[mf][2], alo[mf][2]);
                split_tf32(a3, ahi[mf][3], alo[mf][3]);
            }
            #pragma unroll
            for (int nf = 0; nf < 4; nf++) {
                int col = wn * 32 + nf * 8 + g;
                float b0 = Bs[cur][kk + t4    ][col];
                float b1 = Bs[cur][kk + t4 + 4][col];
                unsigned bh0, bl0, bh1, bl1;
                split_tf32(b0, bh0, bl0);
                split_tf32(b1, bh1, bl1);
                #pragma unroll
                for (int mf = 0; mf < 2; mf++) {
                    mma_tf32(acc[mf][nf], ahi[mf], bh0, bh1);
                    mma_tf32(acc[mf][nf], ahi[mf], bl0, bl1);
                    mma_tf32(acc[mf][nf], alo[mf], bh0, bh1);
                }
            }
        }

        if (more) {
            #pragma unroll
            for (int i = 0; i < 4; i++) {
                int idx = threadIdx.x + i * 256;
                int m = idx >> 4, k = idx & 15;
                As[nxt][m][k] = pa[i];
            }
        }
        __syncthreads();
    }

    #pragma unroll
    for (int mf = 0; mf < 2; mf++) {
        #pragma unroll
        for (int half = 0; half < 2; half++) {
            int m = m0 + wm * 32 + mf * 16 + g + half * 8;
            if (m < COUT) {
                float bv = bias ? bias[m] : 0.f;
                #pragma unroll
                for (int nf = 0; nf < 4; nf++) {
                    int p = p0 + wn * 32 + nf * 8 + 2 * t4;
                    if (p < P) {
                        float2 v;
                        v.x = acc[mf][nf][half * 2 + 0] + bv;
                        v.y = acc[mf][nf][half * 2 + 1] + bv;
                        *(float2*)&Yn[(size_t)m * P + p] = v;
                    }
                }
            }
        }
    }
    if (stats) {
        #pragma unroll
        for (int mf = 0; mf < 2; mf++) {
            #pragma unroll
            for (int half = 0; half < 2; half++) {
                int m = m0 + wm * 32 + mf * 16 + g + half * 8;
                float s = 0.f, s2 = 0.f;
                #pragma unroll
                for (int nf = 0; nf < 4; nf++) {
                    float v0 = acc[mf][nf][half * 2 + 0];
                    float v1 = acc[mf][nf][half * 2 + 1];
                    s  += v0 + v1;
                    s2 += v0 * v0 + v1 * v1;
                }
                s  += __shfl_down_sync(0xffffffffu, s,  1, 4);
                s  += __shfl_down_sync(0xffffffffu, s,  2, 4);
                s2 += __shfl_down_sync(0xffffffffu, s2, 1, 4);
                s2 += __shfl_down_sync(0xffffffffu, s2, 2, 4);
                if (t4 == 0 && m < COUT) {
                    atomicAdd(&stats[m], s);
                    atomicAdd(&stats[64 + m], s2);
                }
            }
        }
    }
}

// ---------------------------------------------------------------------------
// Small GEMM for qk_t (P=64 columns only).
// ---------------------------------------------------------------------------
__global__ __launch_bounds__(256) void sgemm_small(
    const float* __restrict__ X, const float* __restrict__ W,
    const float* __restrict__ bias, float* __restrict__ Y,
    int CIN, int COUT, int P)
{
    const int n  = blockIdx.z;
    const int m0 = blockIdx.y * 64;
    const float* Xn = X + (size_t)n * CIN * P;
    float*       Yn = Y + (size_t)n * COUT * P;

    __shared__ float As[16][68];
    __shared__ float Bs[16][68];
    float acc[4][4];
    #pragma unroll
    for (int i = 0; i < 4; i++)
        #pragma unroll
        for (int j = 0; j < 4; j++) acc[i][j] = 0.f;

    const int tx = threadIdx.x & 15;
    const int ty = threadIdx.x >> 4;

    for (int k0 = 0; k0 < CIN; k0 += 16) {
        for (int i = threadIdx.x; i < 64 * 16; i += 256) {
            int m = i >> 4, k = i & 15;
            float w = 0.f;
            if (m0 + m < COUT) w = W[(size_t)(m0 + m) * CIN + k0 + k];
            As[k][m] = w;
        }
        for (int i = threadIdx.x; i < 16 * 64; i += 256) {
            int k = i >> 6, p = i & 63;
            Bs[k][p] = (p < P) ? Xn[(size_t)(k0 + k) * P + p] : 0.f;
        }
        __syncthreads();
        #pragma unroll
        for (int k = 0; k < 16; k++) {
            float a[4], b[4];
            #pragma unroll
            for (int i = 0; i < 4; i++) a[i] = As[k][ty * 4 + i];
            #pragma unroll
            for (int j = 0; j < 4; j++) b[j] = Bs[k][tx * 4 + j];
            #pragma unroll
            for (int i = 0; i < 4; i++)
                #pragma unroll
                for (int j = 0; j < 4; j++) acc[i][j] += a[i] * b[j];
        }
        __syncthreads();
    }
    #pragma unroll
    for (int i = 0; i < 4; i++) {
        int m = m0 + ty * 4 + i;
        if (m < COUT) {
            float bv = bias ? bias[m] : 0.f;
            #pragma unroll
            for (int j = 0; j < 4; j++) {
                int p = tx * 4 + j;
                if (p < P) Yn[(size_t)m * P + p] = acc[i][j] + bv;
            }
        }
    }
}

// ---------------------------------------------------------------------------
// Fused spatial attention + apply: one block per (n,t).
// att phase: 4x4 register microtile over padded qs/ks rows (147 threads).
// apply phase: xs float4 reads.
// ---------------------------------------------------------------------------
__global__ __launch_bounds__(256) void spatial_fused(
    const float* __restrict__ x, const float* __restrict__ qk,
    const float* __restrict__ att0, const float* __restrict__ alphas,
    float* __restrict__ y)
{
    int b = blockIdx.x;
    int t = b % TT; int n = b / TT;
    __shared__ __align__(16) float qs[3][16][28];
    __shared__ __align__(16) float ks[3][16][28];
    __shared__ __align__(16) float xs[25][68];    // [u][c]
    __shared__ float as[3][25][26];               // [s][u][v]

    const float* base = qk + (size_t)n * 96 * PP + t * VV;
    for (int i = threadIdx.x; i < 48 * 25; i += 256) {
        int c = i / 25, u = i % 25;
        qs[c >> 4][c & 15][u] = base[(size_t)c * PP + u];
        ks[c >> 4][c & 15][u] = base[(size_t)(48 + c) * PP + u];
    }
    // zero the 3-float padding tails so microtile reads are benign
    for (int i = threadIdx.x; i < 48 * 3; i += 256) {
        int c = i / 3, u = 25 + i % 3;
        qs[c >> 4][c & 15][u] = 0.f;
        ks[c >> 4][c & 15][u] = 0.f;
    }
    const float* xb = x + (size_t)n * CC * PP + t * VV;
    for (int i = threadIdx.x; i < 64 * 25; i += 256) {
        int c = i / 25, u = i % 25;
        xs[u][c] = xb[(size_t)c * PP + u];
    }
    __syncthreads();

    // att phase: 4x4 microtile; 3 heads x 7x7 tile-groups = 147 threads
    if (threadIdx.x < 147) {
        int s  = threadIdx.x / 49;
        int r  = threadIdx.x % 49;
        int ug = (r / 7) * 4;
        int vg = (r % 7) * 4;
        float a4[4][4];
        #pragma unroll
        for (int i = 0; i < 4; i++)
            #pragma unroll
            for (int j = 0; j < 4; j++) a4[i][j] = 0.f;
        #pragma unroll
        for (int c = 0; c < 16; c++) {
            float4 qv = *(const float4*)&qs[s][c][ug];
            float4 kv = *(const float4*)&ks[s][c][vg];
            float q[4] = {qv.x, qv.y, qv.z, qv.w};
            float k[4] = {kv.x, kv.y, kv.z, kv.w};
            #pragma unroll
            for (int i = 0; i < 4; i++)
                #pragma unroll
                for (int j = 0; j < 4; j++) a4[i][j] += q[i] * k[j];
        }
        float alpha = alphas[s];
        #pragma unroll
        for (int i = 0; i < 4; i++) {
            int u = ug + i;
            if (u < 25) {
                #pragma unroll
                for (int j = 0; j < 4; j++) {
                    int v = vg + j;
                    if (v < 25)
                        as[s][u][v] = att0[(size_t)s * 625 + u * 25 + v]
                                      + tanh_fast(a4[i][j] * (1.f / 16.f)) * alpha;
                }
            }
        }
    }
    __syncthreads();

    if (threadIdx.x >= 240) return;
    int s  = threadIdx.x / 80;
    int r  = threadIdx.x % 80;
    int cg = r / 5;
    int vg = r % 5;
    float acc[4][5];
    #pragma unroll
    for (int i = 0; i < 4; i++)
        #pragma unroll
        for (int j = 0; j < 5; j++) acc[i][j] = 0.f;
    #pragma unroll
    for (int u = 0; u < 25; u++) {
        float a[4], bb[5];
        *(float4*)a = *(const float4*)&xs[u][cg * 4];
        #pragma unroll
        for (int j = 0; j < 5; j++) bb[j] = as[s][u][vg * 5 + j];
        #pragma unroll
        for (int i = 0; i < 4; i++)
            #pragma unroll
            for (int j = 0; j < 5; j++) acc[i][j] += a[i] * bb[j];
    }
    float* yb = y + (size_t)n * 192 * PP + t * VV;
    #pragma unroll
    for (int i = 0; i < 4; i++) {
        float* yp = yb + (size_t)(s * 64 + cg * 4 + i) * PP + vg * 5;
        #pragma unroll
        for (int j = 0; j < 5; j++) yp[j] = acc[i][j];
    }
}

__global__ void zero_stats_kernel(float* s)
{
    int i = blockIdx.x * blockDim.x + threadIdx.x;
    if (i < 5 * 128) s[i] = 0.f;
}

// out = leaky( res + gamma_c*(conv-mu_c)*rsqrt(var_c+eps) + beta_c ), float4
__global__ __launch_bounds__(256) void bn_apply(
    const float4* __restrict__ conv, const float4* __restrict__ res,
    const float* __restrict__ gamma, const float* __restrict__ beta,
    const float* __restrict__ stats, float4* __restrict__ out)
{
    size_t i = (size_t)blockIdx.x * blockDim.x + threadIdx.x;
    const size_t TOT4 = (size_t)NB * CC * PP / 4;
    if (i >= TOT4) return;
    int c = (int)((i / (PP / 4)) & 63);
    float mu  = stats[c] * (1.f / (float)NTV);
    float var = stats[64 + c] * (1.f / (float)NTV) - mu * mu;
    float g = gamma[c] * rsqrtf(var + 1e-5f);
    float sh = beta[c] - mu * g;
    float4 cv = conv[i], rv = res[i], o;
    float v;
    v = rv.x + cv.x * g + sh; o.x = v > 0.f ? v : 0.1f * v;
    v = rv.y + cv.y * g + sh; o.y = v > 0.f ? v : 0.1f * v;
    v = rv.z + cv.z * g + sh; o.z = v > 0.f ? v : 0.1f * v;
    v = rv.w + cv.w * g + sh; o.w = v > 0.f ? v : 0.1f * v;
    out[i] = o;
}

// ---------------------------------------------------------------------------
// Temporal path
// ---------------------------------------------------------------------------
__global__ void mean_v_kernel(const float* __restrict__ X, float* __restrict__ xb)
{
    int i = blockIdx.x * blockDim.x + threadIdx.x;  // over N*C*T
    if (i >= NB * CC * TT) return;
    const float* p = X + (size_t)i * VV;
    float s = 0.f;
    #pragma unroll
    for (int v = 0; v < VV; v++) s += p[v];
    xb[i] = s * (1.f / (float)VV);
}

__global__ __launch_bounds__(256) void temporal_att(
    const float* __restrict__ qkt, const float* __restrict__ alphaf,
    const float* __restrict__ alphab, float* __restrict__ attt)
{
    int b = blockIdx.x;
    int slot = b & 3; int n = b >> 2;
    int dir = slot >> 1, s = slot & 1;
    int qg = (dir == 0) ? s : 2 + s;
    int kg = (dir == 0) ? 4 + s : 6 + s;
    __shared__ float qs[16][64], ks2[16][64];
    const float* base = qkt + (size_t)n * 128 * TT;
    for (int i = threadIdx.x; i < 16 * 64; i += 256) {
        int c = i >> 6, t = i & 63;
        qs [c][t] = base[(size_t)(qg * 16 + c) * TT + t];
        ks2[c][t] = base[(size_t)(kg * 16 + c) * TT + t];
    }
    __syncthreads();
    float alpha = (dir == 0) ? alphaf[s] : alphab[s];
    float* outp = attt + ((size_t)n * 4 + slot) * TT * TT;
    for (int i = threadIdx.x; i < TT * TT; i += 256) {
        int t = i >> 6, q = i & 63;
        bool keep = (dir == 0) ? (t >= q) : (q >= t);
        float d = 0.f;
        #pragma unroll
        for (int c = 0; c < 16; c++) d += qs[c][t] * ks2[c][q];
        outp[i] = keep ? tanh_fast(d * (1.f / 16.f)) * alpha : 0.f;
    }
}

// ---------------------------------------------------------------------------
// temporal apply as a 3xTF32 MMA GEMM, per (m-tile, slot, n):
//   D[(c,v), q] = sum_t A[(c,v), t] * att[t, q]    M=1600, N=64, K=64
// Block: 32 m-rows x 64 q; 8 warps = 2(m) x 4(n), warp tile 16m x 16n.
// att split hi/lo ONCE per block into smem.
// ---------------------------------------------------------------------------
__global__ __launch_bounds__(256) void temporal_apply_mma(
    const float* __restrict__ tin, const float* __restrict__ attt,
    float* __restrict__ z)
{
    const int mt   = blockIdx.x;          // 0..49
    const int slot = blockIdx.y;          // 0..3
    const int n    = blockIdx.z;
    const int dir = slot >> 1, s = slot & 1;
    const int chbase = dir * 128 + s * 64;
    const int m0g = mt * 32;

    __shared__ __align__(16) float    As [32][68];   // [m][t]
    __shared__ __align__(16) unsigned Bhi[64][68];   // [t][q]
    __shared__ __align__(16) unsigned Blo[64][68];

    const float* tb = tin + (size_t)n * CC * PP;
    const float* ap = attt + ((size_t)n * 4 + slot) * TT * TT;

    // load A (m-major lanes -> ~contiguous 100B runs)
    for (int idx = threadIdx.x; idx < 32 * 64; idx += 256) {
        int m = idx & 31, t = idx >> 5;
        int M = m0g + m, c = M / 25, v = M % 25;
        As[m][t] = tb[(size_t)c * PP + t * 25 + v];
    }
    // load + split att
    for (int idx = threadIdx.x; idx < 64 * 64; idx += 256) {
        int t = idx >> 6, q = idx & 63;
        unsigned h, l;
        split_tf32(ap[idx], h, l);
        Bhi[t][q] = h; Blo[t][q] = l;
    }
    __syncthreads();

    const int lane = threadIdx.x & 31;
    const int warp = threadIdx.x >> 5;
    const int g    = lane >> 2;
    const int t4   = lane & 3;
    const int wm   = warp >> 2;   // 0..1
    const int wn   = warp & 3;    // 0..3

    float acc[2][4];
    #pragma unroll
    for (int j = 0; j < 2; j++)
        #pragma unroll
        for (int c = 0; c < 4; c++) acc[j][c] = 0.f;

    #pragma unroll
    for (int ks = 0; ks < 8; ks++) {
        const int kk = ks * 8;
        unsigned ahi[4], alo[4];
        int r = wm * 16 + g;
        float a0 = As[r    ][kk + t4];
        float a1 = As[r + 8][kk + t4];
        float a2 = As[r    ][kk + t4 + 4];
        float a3 = As[r + 8][kk + t4 + 4];
        split_tf32(a0, ahi[0], alo[0]);
        split_tf32(a1, ahi[1], alo[1]);
        split_tf32(a2, ahi[2], alo[2]);
        split_tf32(a3, ahi[3], alo[3]);
        #pragma unroll
        for (int nf = 0; nf < 2; nf++) {
            int col = wn * 16 + nf * 8 + g;
            unsigned bh0 = Bhi[kk + t4    ][col];
            unsigned bh1 = Bhi[kk + t4 + 4][col];
            unsigned bl0 = Blo[kk + t4    ][col];
            unsigned bl1 = Blo[kk + t4 + 4][col];
            mma_tf32(acc[nf], ahi, bh0, bh1);
            mma_tf32(acc[nf], ahi, bl0, bl1);
            mma_tf32(acc[nf], alo, bh0, bh1);
        }
    }

    // epilogue: scatter to z
    float* zb = z + (size_t)n * 256 * PP;
    #pragma unroll
    for (int half = 0; half < 2; half++) {
        int m = wm * 16 + g + half * 8;
        int M = m0g + m, c = M / 25, v = M % 25;
        float* zp = zb + (size_t)(chbase + c) * PP + v;
        #pragma unroll
        for (int nf = 0; nf < 2; nf++) {
            int q = wn * 16 + nf * 8 + 2 * t4;
            zp[(size_t)q * 25]       = acc[nf][half * 2 + 0];
            zp[(size_t)(q + 1) * 25] = acc[nf][half * 2 + 1];
        }
    }
}

// ---------------------------------------------------------------------------
// Launcher
// ---------------------------------------------------------------------------
static float* sym(const void* symbol)
{
    void* p = nullptr;
    cudaGetSymbolAddress(&p, symbol);
    return (float*)p;
}

extern "C" void kernel_launch(void* const* d_in, const int* in_sizes, int n_in,
                              void* d_out, int out_size)
{
    const float* x       = (const float*)d_in[0];
    const float* att0s   = (const float*)d_in[1];
    const float* alphas  = (const float*)d_in[2];
    const float* W_qk_s  = (const float*)d_in[3];
    const float* b_qk_s  = (const float*)d_in[4];
    const float* W_outs  = (const float*)d_in[5];
    const float* g_outs  = (const float*)d_in[7];
    const float* be_outs = (const float*)d_in[8];
    const float* W_ffs   = (const float*)d_in[9];
    const float* g_ffs   = (const float*)d_in[11];
    const float* be_ffs  = (const float*)d_in[12];
    const float* W_qk_t  = (const float*)d_in[13];
    const float* b_qk_t  = (const float*)d_in[14];
    const float* al_f    = (const float*)d_in[15];
    const float* al_b    = (const float*)d_in[16];
    const float* W_outt  = (const float*)d_in[17];
    const float* g_outt  = (const float*)d_in[19];
    const float* be_outt = (const float*)d_in[20];
    const float* W_fft   = (const float*)d_in[21];
    const float* g_fft   = (const float*)d_in[23];
    const float* be_fft  = (const float*)d_in[24];
    const float* W_tcn   = (const float*)d_in[25];
    const float* g_tcn   = (const float*)d_in[27];
    const float* be_tcn  = (const float*)d_in[28];
    float* out = (float*)d_out;

    float* p_qk   = sym(g_qk);
    float* p_y    = sym(g_y);
    float* p_conv = sym(g_conv);
    float* p_sout = sym(g_sout);
    float* p_b1   = sym(g_b1);
    float* p_b2   = sym(g_b2);
    float* p_xbar = sym(g_xbar);
    float* p_qkt  = sym(g_qkt);
    float* p_attt = sym(g_attt);
    float* p_z    = sym(g_z);
    float* p_st   = sym(g_stats);

    const size_t TOT = (size_t)NB * CC * PP;
    const int EW_BLOCKS4 = (int)((TOT / 4 + 255) / 256);
    const dim3 G13(13, 1, NB);

    zero_stats_kernel<<<3, 256>>>(p_st);

    // --- spatial attention (fused att + apply) ---
    sgemm_tf32<0><<<dim3(13, 2, NB), 256>>>(x, W_qk_s, b_qk_s, p_qk, 64, 96, nullptr);
    spatial_fused<<<NB * TT, 256>>>(x, p_qk, att0s, alphas, p_y);

    // y = BN(conv(y, W_outs)); y = leaky(x + y)   [bias cancels in BN]
    sgemm_tf32<0><<<G13, 256>>>(p_y, W_outs, nullptr, p_conv, 192, 64, p_st + 0);
    bn_apply<<<EW_BLOCKS4, 256>>>((const float4*)p_conv, (const float4*)x,
                                  g_outs, be_outs, p_st + 0, (float4*)p_b1);

    // y = BN(conv(y, W_ffs)); s_out = leaky(x + y)
    sgemm_tf32<0><<<G13, 256>>>(p_b1, W_ffs, nullptr, p_conv, 64, 64, p_st + 128);
    bn_apply<<<EW_BLOCKS4, 256>>>((const float4*)p_conv, (const float4*)x,
                                  g_ffs, be_ffs, p_st + 128, (float4*)p_sout);

    // --- temporal attention ---
    mean_v_kernel<<<(NB * CC * TT + 255) / 256, 256>>>(p_sout, p_xbar);
    sgemm_small<<<dim3(1, 2, NB), 256>>>(p_xbar, W_qk_t, b_qk_t, p_qkt, 64, 128, TT);
    temporal_att<<<NB * 4, 256>>>(p_qkt, al_f, al_b, p_attt);
    temporal_apply_mma<<<dim3(50, 4, NB), 256>>>(p_sout, p_attt, p_z);

    // z = BN(conv(z, W_outt)); z = leaky(t_in + z)
    sgemm_tf32<0><<<G13, 256>>>(p_z, W_outt, nullptr, p_conv, 256, 64, p_st + 256);
    bn_apply<<<EW_BLOCKS4, 256>>>((const float4*)p_conv, (const float4*)p_sout,
                                  g_outt, be_outt, p_st + 256, (float4*)p_b1);

    // z = BN(conv(z, W_fft)); z = leaky(t_in + z)
    sgemm_tf32<0><<<G13, 256>>>(p_b1, W_fft, nullptr, p_conv, 64, 64, p_st + 384);
    bn_apply<<<EW_BLOCKS4, 256>>>((const float4*)p_conv, (const float4*)p_sout,
                                  g_fft, be_fft, p_st + 384, (float4*)p_b2);

    // --- TCN as K=448 GEMM (k = c*7+dt, shifted B rows) ---
    sgemm_tf32<1><<<G13, 256>>>(p_b2, W_tcn, nullptr, p_conv, 448, 64, p_st + 512);
    bn_apply<<<EW_BLOCKS4, 256>>>((const float4*)p_conv, (const float4*)p_b2,
                                  g_tcn, be_tcn, p_st + 512, (float4*)out);
}

// round 16
// speedup vs baseline: 1.4331x; 1.0818x over previous
#include <cuda_runtime.h>
#include <cuda_bf16.h>
#include <math.h>
#include <cstdint>

// ---------------------------------------------------------------------------
// Problem constants
// ---------------------------------------------------------------------------
#define NB   128          // batch N
#define CC   64           // channels C = O
#define TT   64           // T
#define VV   25           // V
#define PP   (TT*VV)      // 1600 positions per (n, channel)
#define SS   3            // spatial heads
#define NTV  (NB*TT*VV)   // 204800 samples per channel for BN

// ---------------------------------------------------------------------------
// Scratch (device globals; no allocation allowed)
// ---------------------------------------------------------------------------
__device__ float g_qk  [ (size_t)NB*96*PP ];        // spatial qk conv out
__device__ float g_y   [ (size_t)NB*192*PP ];       // spatial attended
__device__ float g_conv[ (size_t)NB*CC*PP ];        // generic conv output
__device__ float g_sout[ (size_t)NB*CC*PP ];        // s_out == t_in
__device__ float g_b1  [ (size_t)NB*CC*PP ];
__device__ float g_b2  [ (size_t)NB*CC*PP ];
__device__ float g_xbar[ (size_t)NB*CC*TT ];        // mean over V
__device__ float g_qkt [ (size_t)NB*128*TT ];
__device__ float g_attt[ (size_t)NB*4*TT*TT ];      // 4 slots: f0,f1,b0,b1
__device__ float g_z   [ (size_t)NB*256*PP ];       // temporal attended
__device__ float g_stats[5*128];                    // 5 BNs x (sum[64], sumsq[64])

// ---------------------------------------------------------------------------
// cp.async helpers
// ---------------------------------------------------------------------------
__device__ __forceinline__ unsigned int smem_u32(const void* p)
{
    return (unsigned int)__cvta_generic_to_shared(p);
}
__device__ __forceinline__ void cp16(unsigned int dst, const void* src, int sbytes)
{
    asm volatile("cp.async.cg.shared.global [%0], [%1], 16, %2;"
                 :: "r"(dst), "l"(src), "r"(sbytes));
}
__device__ __forceinline__ void cp4(unsigned int dst, const void* src, int sbytes)
{
    asm volatile("cp.async.ca.shared.global [%0], [%1], 4, %2;"
                 :: "r"(dst), "l"(src), "r"(sbytes));
}
__device__ __forceinline__ void cp_commit()
{
    asm volatile("cp.async.commit_group;");
}
template<int N>
__device__ __forceinline__ void cp_wait()
{
    asm volatile("cp.async.wait_group %0;" :: "n"(N));
}

// ---------------------------------------------------------------------------
// tf32 helpers (still used by temporal_apply_mma)
// ---------------------------------------------------------------------------
__device__ __forceinline__ void split_tf32(float x, unsigned& hi, unsigned& lo)
{
    asm("cvt.rna.tf32.f32 %0, %1;" : "=r"(hi) : "f"(x));
    float r = x - __uint_as_float(hi);
    asm("cvt.rna.tf32.f32 %0, %1;" : "=r"(lo) : "f"(r));
}
__device__ __forceinline__ void mma_tf32(float* c, const unsigned* a,
                                         unsigned b0, unsigned b1)
{
    asm volatile(
        "mma.sync.aligned.m16n8k8.row.col.f32.tf32.tf32.f32 "
        "{%0,%1,%2,%3}, {%4,%5,%6,%7}, {%8,%9}, {%0,%1,%2,%3};"
        : "+f"(c[0]), "+f"(c[1]), "+f"(c[2]), "+f"(c[3])
        : "r"(a[0]), "r"(a[1]), "r"(a[2]), "r"(a[3]), "r"(b0), "r"(b1));
}
__device__ __forceinline__ float tanh_fast(float x)
{
    float y;
    asm("tanh.approx.f32 %0, %1;" : "=f"(y) : "f"(x));
    return y;
}

// ---------------------------------------------------------------------------
// bf16 helpers: split a float pair into packed bf16x2 hi/lo (element k-even
// in the LOW 16 bits, matching the mma fragment order).
// ---------------------------------------------------------------------------
__device__ __forceinline__ void split_bf16x2(float x0, float x1,
                                             unsigned& hi, unsigned& lo)
{
    __nv_bfloat162 h = __floats2bfloat162_rn(x0, x1);      // x0 -> low half
    float h0 = __bfloat162float(__low2bfloat16(h));
    float h1 = __bfloat162float(__high2bfloat16(h));
    __nv_bfloat162 l = __floats2bfloat162_rn(x0 - h0, x1 - h1);
    hi = *reinterpret_cast<unsigned*>(&h);
    lo = *reinterpret_cast<unsigned*>(&l);
}
__device__ __forceinline__ void mma_bf16(float* c, const unsigned* a,
                                         unsigned b0, unsigned b1)
{
    asm volatile(
        "mma.sync.aligned.m16n8k16.row.col.f32.bf16.bf16.f32 "
        "{%0,%1,%2,%3}, {%4,%5,%6,%7}, {%8,%9}, {%0,%1,%2,%3};"
        : "+f"(c[0]), "+f"(c[1]), "+f"(c[2]), "+f"(c[3])
        : "r"(a[0]), "r"(a[1]), "r"(a[2]), "r"(a[3]), "r"(b0), "r"(b1));
}

// ---------------------------------------------------------------------------
// Tensor-core GEMM (3x BF16, m16n8k16) for 1x1 convs and the TCN-as-GEMM.
//   Y[n][m][p] = sum_k A[m][k] * B[k][p]      (per n)
// hi/lo bf16 decomposition (hi*hi + hi*lo + lo*hi): dropped term ~2^-18.
// A split ONCE in registers during global->smem staging (packed bf16x2
// along k); B split ONCE per tile in a smem pass. Mainloop fragment loads
// are plain LDS.32 of packed operands -> no per-fragment cvt chains.
// Tile: BM=64, BN=128, BK=16 (one k16 mma group per tile); 8 warps 2m x 4n.
// grid: (13, ceil(COUT/64), NB). Fused BN stats (bias must be nullptr).
// Phantom columns (p0+p >= P) stay zero (cp.async zfill) -> clean stats.
// ---------------------------------------------------------------------------
template<int TCN>
__global__ __launch_bounds__(256, 2) void sgemm_bf16(
    const float* __restrict__ X, const float* __restrict__ W,
    const float* __restrict__ bias, float* __restrict__ Y,
    int CIN, int COUT, float* __restrict__ stats)
{
    const int P  = PP;
    const int n  = blockIdx.z;
    const int m0 = blockIdx.y * 64;
    const int p0 = blockIdx.x * 128;
    const float* Xn = X + (size_t)n * (TCN ? 64 : CIN) * P;
    float*       Yn = Y + (size_t)n * COUT * P;

    // A: packed bf16x2 along k, [m][k2] stride 12 (conflict-free fragments)
    __shared__ __align__(16) unsigned Ahi[2][64][12];
    __shared__ __align__(16) unsigned Alo[2][64][12];
    __shared__ __align__(16) float    Bs [2][16][132];   // raw f32 landing
    __shared__ __align__(16) unsigned Bhi[2][8][132];    // packed [k2][p]
    __shared__ __align__(16) unsigned Blo[2][8][132];

    float acc[2][4][4];
    #pragma unroll
    for (int i = 0; i < 2; i++)
        #pragma unroll
        for (int j = 0; j < 4; j++)
            #pragma unroll
            for (int c = 0; c < 4; c++) acc[i][j][c] = 0.f;

    const int lane = threadIdx.x & 31;
    const int warp = threadIdx.x >> 5;
    const int g    = lane >> 2;
    const int t4   = lane & 3;
    const int wm   = warp >> 2;   // 0..1
    const int wn   = warp & 3;    // 0..3

    const int nk = CIN / 16;
    unsigned pah[2], pal[2];

    auto issueB = [&](int kt, int buf) {
        const int k0 = kt * 16;
        if (!TCN) {
            #pragma unroll
            for (int i = 0; i < 2; i++) {
                int f = threadIdx.x + i * 256;
                int k = f >> 5, p = (f & 31) * 4;
                bool ok = (p0 + p) < P;
                const float* src = ok ? &Xn[(size_t)(k0 + k) * P + p0 + p] : Xn;
                cp16(smem_u32(&Bs[buf][k][p]), src, ok ? 16 : 0);
            }
        } else {
            #pragma unroll
            for (int i = 0; i < 8; i++) {
                int idx = threadIdx.x + i * 256;
                int k = idx >> 7, p = idx & 127;
                int kk = k0 + k;
                int c = kk / 7, dt = kk % 7;
                int src = p0 + p + (dt - 3) * 25;
                bool ok = (p0 + p) < P && src >= 0 && src < P;
                const float* sp = ok ? &Xn[(size_t)c * P + src] : Xn;
                cp4(smem_u32(&Bs[buf][k][p]), sp, ok ? 4 : 0);
            }
        }
        cp_commit();
    };

    auto stageA = [&](int kt) {
        const int k0 = kt * 16;
        #pragma unroll
        for (int i = 0; i < 2; i++) {
            int pi = threadIdx.x + i * 256;   // 0..511 k-pairs
            int m = pi >> 3, k2 = pi & 7;
            float x0 = 0.f, x1 = 0.f;
            if (m0 + m < COUT) {
                const float* wp = &W[(size_t)(m0 + m) * CIN + k0 + 2 * k2];
                x0 = wp[0]; x1 = wp[1];
            }
            split_bf16x2(x0, x1, pah[i], pal[i]);
        }
    };
    auto storeA = [&](int buf) {
        #pragma unroll
        for (int i = 0; i < 2; i++) {
            int pi = threadIdx.x + i * 256;
            int m = pi >> 3, k2 = pi & 7;
            Ahi[buf][m][k2] = pah[i];
            Alo[buf][m][k2] = pal[i];
        }
    };

    // ---- prologue: tile 0 ----
    stageA(0);
    storeA(0);
    issueB(0, 0);

    for (int it = 0; it < nk; it++) {
        const int cur = it & 1;
        const int nxt = 1 - cur;
        const bool more = (it + 1 < nk);

        if (more) {
            issueB(it + 1, nxt);
            stageA(it + 1);
        }

        if (more) cp_wait<1>(); else cp_wait<0>();
        __syncthreads();

        // ---- B split pass: Bs[cur] f32 -> packed Bhi/Blo[cur] ----
        #pragma unroll
        for (int i = 0; i < 4; i++) {
            int pi = threadIdx.x + i * 256;   // 0..1023
            int k2 = pi >> 7, col = pi & 127;
            unsigned bh, bl;
            split_bf16x2(Bs[cur][2 * k2][col], Bs[cur][2 * k2 + 1][col], bh, bl);
            Bhi[cur][k2][col] = bh;
            Blo[cur][k2][col] = bl;
        }
        __syncthreads();

        // ---- compute: one m16n8k16 group per tile ----
        unsigned ahi[2][4], alo[2][4];
        #pragma unroll
        for (int mf = 0; mf < 2; mf++) {
            int r = wm * 32 + mf * 16 + g;
            ahi[mf][0] = Ahi[cur][r    ][t4];
            ahi[mf][1] = Ahi[cur][r + 8][t4];
            ahi[mf][2] = Ahi[cur][r    ][t4 + 4];
            ahi[mf][3] = Ahi[cur][r + 8][t4 + 4];
            alo[mf][0] = Alo[cur][r    ][t4];
            alo[mf][1] = Alo[cur][r + 8][t4];
            alo[mf][2] = Alo[cur][r    ][t4 + 4];
            alo[mf][3] = Alo[cur][r + 8][t4 + 4];
        }
        #pragma unroll
        for (int nf = 0; nf < 4; nf++) {
            int col = wn * 32 + nf * 8 + g;
            unsigned bh0 = Bhi[cur][t4    ][col];
            unsigned bh1 = Bhi[cur][t4 + 4][col];
            unsigned bl0 = Blo[cur][t4    ][col];
            unsigned bl1 = Blo[cur][t4 + 4][col];
            #pragma unroll
            for (int mf = 0; mf < 2; mf++) {
                mma_bf16(acc[mf][nf], ahi[mf], bh0, bh1);
                mma_bf16(acc[mf][nf], ahi[mf], bl0, bl1);
                mma_bf16(acc[mf][nf], alo[mf], bh0, bh1);
            }
        }

        if (more) storeA(nxt);
        __syncthreads();
    }

    // ---- epilogue: fragment rows -> global ----
    #pragma unroll
    for (int mf = 0; mf < 2; mf++) {
        #pragma unroll
        for (int half = 0; half < 2; half++) {
            int m = m0 + wm * 32 + mf * 16 + g + half * 8;
            if (m < COUT) {
                float bv = bias ? bias[m] : 0.f;
                #pragma unroll
                for (int nf = 0; nf < 4; nf++) {
                    int p = p0 + wn * 32 + nf * 8 + 2 * t4;
                    if (p < P) {
                        float2 v;
                        v.x = acc[mf][nf][half * 2 + 0] + bv;
                        v.y = acc[mf][nf][half * 2 + 1] + bv;
                        *(float2*)&Yn[(size_t)m * P + p] = v;
                    }
                }
            }
        }
    }
    if (stats) {
        #pragma unroll
        for (int mf = 0; mf < 2; mf++) {
            #pragma unroll
            for (int half = 0; half < 2; half++) {
                int m = m0 + wm * 32 + mf * 16 + g + half * 8;
                float s = 0.f, s2 = 0.f;
                #pragma unroll
                for (int nf = 0; nf < 4; nf++) {
                    float v0 = acc[mf][nf][half * 2 + 0];
                    float v1 = acc[mf][nf][half * 2 + 1];
                    s  += v0 + v1;
                    s2 += v0 * v0 + v1 * v1;
                }
                s  += __shfl_down_sync(0xffffffffu, s,  1, 4);
                s  += __shfl_down_sync(0xffffffffu, s,  2, 4);
                s2 += __shfl_down_sync(0xffffffffu, s2, 1, 4);
                s2 += __shfl_down_sync(0xffffffffu, s2, 2, 4);
                if (t4 == 0 && m < COUT) {
                    atomicAdd(&stats[m], s);
                    atomicAdd(&stats[64 + m], s2);
                }
            }
        }
    }
}

// ---------------------------------------------------------------------------
// Small GEMM for qk_t (P=64 columns only).
// ---------------------------------------------------------------------------
__global__ __launch_bounds__(256) void sgemm_small(
    const float* __restrict__ X, const float* __restrict__ W,
    const float* __restrict__ bias, float* __restrict__ Y,
    int CIN, int COUT, int P)
{
    const int n  = blockIdx.z;
    const int m0 = blockIdx.y * 64;
    const float* Xn = X + (size_t)n * CIN * P;
    float*       Yn = Y + (size_t)n * COUT * P;

    __shared__ float As[16][68];
    __shared__ float Bs[16][68];
    float acc[4][4];
    #pragma unroll
    for (int i = 0; i < 4; i++)
        #pragma unroll
        for (int j = 0; j < 4; j++) acc[i][j] = 0.f;

    const int tx = threadIdx.x & 15;
    const int ty = threadIdx.x >> 4;

    for (int k0 = 0; k0 < CIN; k0 += 16) {
        for (int i = threadIdx.x; i < 64 * 16; i += 256) {
            int m = i >> 4, k = i & 15;
            float w = 0.f;
            if (m0 + m < COUT) w = W[(size_t)(m0 + m) * CIN + k0 + k];
            As[k][m] = w;
        }
        for (int i = threadIdx.x; i < 16 * 64; i += 256) {
            int k = i >> 6, p = i & 63;
            Bs[k][p] = (p < P) ? Xn[(size_t)(k0 + k) * P + p] : 0.f;
        }
        __syncthreads();
        #pragma unroll
        for (int k = 0; k < 16; k++) {
            float a[4], b[4];
            #pragma unroll
            for (int i = 0; i < 4; i++) a[i] = As[k][ty * 4 + i];
            #pragma unroll
            for (int j = 0; j < 4; j++) b[j] = Bs[k][tx * 4 + j];
            #pragma unroll
            for (int i = 0; i < 4; i++)
                #pragma unroll
                for (int j = 0; j < 4; j++) acc[i][j] += a[i] * b[j];
        }
        __syncthreads();
    }
    #pragma unroll
    for (int i = 0; i < 4; i++) {
        int m = m0 + ty * 4 + i;
        if (m < COUT) {
            float bv = bias ? bias[m] : 0.f;
            #pragma unroll
            for (int j = 0; j < 4; j++) {
                int p = tx * 4 + j;
                if (p < P) Yn[(size_t)m * P + p] = acc[i][j] + bv;
            }
        }
    }
}

// ---------------------------------------------------------------------------
// Fused spatial attention + apply: one block per (n,t).
// ---------------------------------------------------------------------------
__global__ __launch_bounds__(256) void spatial_fused(
    const float* __restrict__ x, const float* __restrict__ qk,
    const float* __restrict__ att0, const float* __restrict__ alphas,
    float* __restrict__ y)
{
    int b = blockIdx.x;
    int t = b % TT; int n = b / TT;
    __shared__ __align__(16) float qs[3][16][28];
    __shared__ __align__(16) float ks[3][16][28];
    __shared__ __align__(16) float xs[25][68];    // [u][c]
    __shared__ float as[3][25][26];               // [s][u][v]

    const float* base = qk + (size_t)n * 96 * PP + t * VV;
    for (int i = threadIdx.x; i < 48 * 25; i += 256) {
        int c = i / 25, u = i % 25;
        qs[c >> 4][c & 15][u] = base[(size_t)c * PP + u];
        ks[c >> 4][c & 15][u] = base[(size_t)(48 + c) * PP + u];
    }
    for (int i = threadIdx.x; i < 48 * 3; i += 256) {
        int c = i / 3, u = 25 + i % 3;
        qs[c >> 4][c & 15][u] = 0.f;
        ks[c >> 4][c & 15][u] = 0.f;
    }
    const float* xb = x + (size_t)n * CC * PP + t * VV;
    for (int i = threadIdx.x; i < 64 * 25; i += 256) {
        int c = i / 25, u = i % 25;
        xs[u][c] = xb[(size_t)c * PP + u];
    }
    __syncthreads();

    if (threadIdx.x < 147) {
        int s  = threadIdx.x / 49;
        int r  = threadIdx.x % 49;
        int ug = (r / 7) * 4;
        int vg = (r % 7) * 4;
        float a4[4][4];
        #pragma unroll
        for (int i = 0; i < 4; i++)
            #pragma unroll
            for (int j = 0; j < 4; j++) a4[i][j] = 0.f;
        #pragma unroll
        for (int c = 0; c < 16; c++) {
            float4 qv = *(const float4*)&qs[s][c][ug];
            float4 kv = *(const float4*)&ks[s][c][vg];
            float q[4] = {qv.x, qv.y, qv.z, qv.w};
            float k[4] = {kv.x, kv.y, kv.z, kv.w};
            #pragma unroll
            for (int i = 0; i < 4; i++)
                #pragma unroll
                for (int j = 0; j < 4; j++) a4[i][j] += q[i] * k[j];
        }
        float alpha = alphas[s];
        #pragma unroll
        for (int i = 0; i < 4; i++) {
            int u = ug + i;
            if (u < 25) {
                #pragma unroll
                for (int j = 0; j < 4; j++) {
                    int v = vg + j;
                    if (v < 25)
                        as[s][u][v] = att0[(size_t)s * 625 + u * 25 + v]
                                      + tanh_fast(a4[i][j] * (1.f / 16.f)) * alpha;
                }
            }
        }
    }
    __syncthreads();

    if (threadIdx.x >= 240) return;
    int s  = threadIdx.x / 80;
    int r  = threadIdx.x % 80;
    int cg = r / 5;
    int vg = r % 5;
    float acc[4][5];
    #pragma unroll
    for (int i = 0; i < 4; i++)
        #pragma unroll
        for (int j = 0; j < 5; j++) acc[i][j] = 0.f;
    #pragma unroll
    for (int u = 0; u < 25; u++) {
        float a[4], bb[5];
        *(float4*)a = *(const float4*)&xs[u][cg * 4];
        #pragma unroll
        for (int j = 0; j < 5; j++) bb[j] = as[s][u][vg * 5 + j];
        #pragma unroll
        for (int i = 0; i < 4; i++)
            #pragma unroll
            for (int j = 0; j < 5; j++) acc[i][j] += a[i] * bb[j];
    }
    float* yb = y + (size_t)n * 192 * PP + t * VV;
    #pragma unroll
    for (int i = 0; i < 4; i++) {
        float* yp = yb + (size_t)(s * 64 + cg * 4 + i) * PP + vg * 5;
        #pragma unroll
        for (int j = 0; j < 5; j++) yp[j] = acc[i][j];
    }
}

__global__ void zero_stats_kernel(float* s)
{
    int i = blockIdx.x * blockDim.x + threadIdx.x;
    if (i < 5 * 128) s[i] = 0.f;
}

// out = leaky( res + gamma_c*(conv-mu_c)*rsqrt(var_c+eps) + beta_c ), float4
__global__ __launch_bounds__(256) void bn_apply(
    const float4* __restrict__ conv, const float4* __restrict__ res,
    const float* __restrict__ gamma, const float* __restrict__ beta,
    const float* __restrict__ stats, float4* __restrict__ out)
{
    size_t i = (size_t)blockIdx.x * blockDim.x + threadIdx.x;
    const size_t TOT4 = (size_t)NB * CC * PP / 4;
    if (i >= TOT4) return;
    int c = (int)((i / (PP / 4)) & 63);
    float mu  = stats[c] * (1.f / (float)NTV);
    float var = stats[64 + c] * (1.f / (float)NTV) - mu * mu;
    float g = gamma[c] * rsqrtf(var + 1e-5f);
    float sh = beta[c] - mu * g;
    float4 cv = conv[i], rv = res[i], o;
    float v;
    v = rv.x + cv.x * g + sh; o.x = v > 0.f ? v : 0.1f * v;
    v = rv.y + cv.y * g + sh; o.y = v > 0.f ? v : 0.1f * v;
    v = rv.z + cv.z * g + sh; o.z = v > 0.f ? v : 0.1f * v;
    v = rv.w + cv.w * g + sh; o.w = v > 0.f ? v : 0.1f * v;
    out[i] = o;
}

// ---------------------------------------------------------------------------
// Temporal path
// ---------------------------------------------------------------------------
__global__ void mean_v_kernel(const float* __restrict__ X, float* __restrict__ xb)
{
    int i = blockIdx.x * blockDim.x + threadIdx.x;  // over N*C*T
    if (i >= NB * CC * TT) return;
    const float* p = X + (size_t)i * VV;
    float s = 0.f;
    #pragma unroll
    for (int v = 0; v < VV; v++) s += p[v];
    xb[i] = s * (1.f / (float)VV);
}

__global__ __launch_bounds__(256) void temporal_att(
    const float* __restrict__ qkt, const float* __restrict__ alphaf,
    const float* __restrict__ alphab, float* __restrict__ attt)
{
    int b = blockIdx.x;
    int slot = b & 3; int n = b >> 2;
    int dir = slot >> 1, s = slot & 1;
    int qg = (dir == 0) ? s : 2 + s;
    int kg = (dir == 0) ? 4 + s : 6 + s;
    __shared__ float qs[16][64], ks2[16][64];
    const float* base = qkt + (size_t)n * 128 * TT;
    for (int i = threadIdx.x; i < 16 * 64; i += 256) {
        int c = i >> 6, t = i & 63;
        qs [c][t] = base[(size_t)(qg * 16 + c) * TT + t];
        ks2[c][t] = base[(size_t)(kg * 16 + c) * TT + t];
    }
    __syncthreads();
    float alpha = (dir == 0) ? alphaf[s] : alphab[s];
    float* outp = attt + ((size_t)n * 4 + slot) * TT * TT;
    for (int i = threadIdx.x; i < TT * TT; i += 256) {
        int t = i >> 6, q = i & 63;
        bool keep = (dir == 0) ? (t >= q) : (q >= t);
        float d = 0.f;
        #pragma unroll
        for (int c = 0; c < 16; c++) d += qs[c][t] * ks2[c][q];
        outp[i] = keep ? tanh_fast(d * (1.f / 16.f)) * alpha : 0.f;
    }
}

// ---------------------------------------------------------------------------
// temporal apply as a 3xTF32 MMA GEMM (unchanged from 1590us baseline)
// ---------------------------------------------------------------------------
__global__ __launch_bounds__(256) void temporal_apply_mma(
    const float* __restrict__ tin, const float* __restrict__ attt,
    float* __restrict__ z)
{
    const int mt   = blockIdx.x;          // 0..49
    const int slot = blockIdx.y;          // 0..3
    const int n    = blockIdx.z;
    const int dir = slot >> 1, s = slot & 1;
    const int chbase = dir * 128 + s * 64;
    const int m0g = mt * 32;

    __shared__ __align__(16) float    As [32][68];   // [m][t]
    __shared__ __align__(16) unsigned Bhi[64][68];   // [t][q]
    __shared__ __align__(16) unsigned Blo[64][68];

    const float* tb = tin + (size_t)n * CC * PP;
    const float* ap = attt + ((size_t)n * 4 + slot) * TT * TT;

    for (int idx = threadIdx.x; idx < 32 * 64; idx += 256) {
        int m = idx & 31, t = idx >> 5;
        int M = m0g + m, c = M / 25, v = M % 25;
        As[m][t] = tb[(size_t)c * PP + t * 25 + v];
    }
    for (int idx = threadIdx.x; idx < 64 * 64; idx += 256) {
        int t = idx >> 6, q = idx & 63;
        unsigned h, l;
        split_tf32(ap[idx], h, l);
        Bhi[t][q] = h; Blo[t][q] = l;
    }
    __syncthreads();

    const int lane = threadIdx.x & 31;
    const int warp = threadIdx.x >> 5;
    const int g    = lane >> 2;
    const int t4   = lane & 3;
    const int wm   = warp >> 2;   // 0..1
    const int wn   = warp & 3;    // 0..3

    float acc[2][4];
    #pragma unroll
    for (int j = 0; j < 2; j++)
        #pragma unroll
        for (int c = 0; c < 4; c++) acc[j][c] = 0.f;

    #pragma unroll
    for (int ks = 0; ks < 8; ks++) {
        const int kk = ks * 8;
        unsigned ahi[4], alo[4];
        int r = wm * 16 + g;
        float a0 = As[r    ][kk + t4];
        float a1 = As[r + 8][kk + t4];
        float a2 = As[r    ][kk + t4 + 4];
        float a3 = As[r + 8][kk + t4 + 4];
        split_tf32(a0, ahi[0], alo[0]);
        split_tf32(a1, ahi[1], alo[1]);
        split_tf32(a2, ahi[2], alo[2]);
        split_tf32(a3, ahi[3], alo[3]);
        #pragma unroll
        for (int nf = 0; nf < 2; nf++) {
            int col = wn * 16 + nf * 8 + g;
            unsigned bh0 = Bhi[kk + t4    ][col];
            unsigned bh1 = Bhi[kk + t4 + 4][col];
            unsigned bl0 = Blo[kk + t4    ][col];
            unsigned bl1 = Blo[kk + t4 + 4][col];
            mma_tf32(acc[nf], ahi, bh0, bh1);
            mma_tf32(acc[nf], ahi, bl0, bl1);
            mma_tf32(acc[nf], alo, bh0, bh1);
        }
    }

    float* zb = z + (size_t)n * 256 * PP;
    #pragma unroll
    for (int half = 0; half < 2; half++) {
        int m = wm * 16 + g + half * 8;
        int M = m0g + m, c = M / 25, v = M % 25;
        float* zp = zb + (size_t)(chbase + c) * PP + v;
        #pragma unroll
        for (int nf = 0; nf < 2; nf++) {
            int q = wn * 16 + nf * 8 + 2 * t4;
            zp[(size_t)q * 25]       = acc[nf][half * 2 + 0];
            zp[(size_t)(q + 1) * 25] = acc[nf][half * 2 + 1];
        }
    }
}

// ---------------------------------------------------------------------------
// Launcher
// ---------------------------------------------------------------------------
static float* sym(const void* symbol)
{
    void* p = nullptr;
    cudaGetSymbolAddress(&p, symbol);
    return (float*)p;
}

extern "C" void kernel_launch(void* const* d_in, const int* in_sizes, int n_in,
                              void* d_out, int out_size)
{
    const float* x       = (const float*)d_in[0];
    const float* att0s   = (const float*)d_in[1];
    const float* alphas  = (const float*)d_in[2];
    const float* W_qk_s  = (const float*)d_in[3];
    const float* b_qk_s  = (const float*)d_in[4];
    const float* W_outs  = (const float*)d_in[5];
    const float* g_outs  = (const float*)d_in[7];
    const float* be_outs = (const float*)d_in[8];
    const float* W_ffs   = (const float*)d_in[9];
    const float* g_ffs   = (const float*)d_in[11];
    const float* be_ffs  = (const float*)d_in[12];
    const float* W_qk_t  = (const float*)d_in[13];
    const float* b_qk_t  = (const float*)d_in[14];
    const float* al_f    = (const float*)d_in[15];
    const float* al_b    = (const float*)d_in[16];
    const float* W_outt  = (const float*)d_in[17];
    const float* g_outt  = (const float*)d_in[19];
    const float* be_outt = (const float*)d_in[20];
    const float* W_fft   = (const float*)d_in[21];
    const float* g_fft   = (const float*)d_in[23];
    const float* be_fft  = (const float*)d_in[24];
    const float* W_tcn   = (const float*)d_in[25];
    const float* g_tcn   = (const float*)d_in[27];
    const float* be_tcn  = (const float*)d_in[28];
    float* out = (float*)d_out;

    float* p_qk   = sym(g_qk);
    float* p_y    = sym(g_y);
    float* p_conv = sym(g_conv);
    float* p_sout = sym(g_sout);
    float* p_b1   = sym(g_b1);
    float* p_b2   = sym(g_b2);
    float* p_xbar = sym(g_xbar);
    float* p_qkt  = sym(g_qkt);
    float* p_attt = sym(g_attt);
    float* p_z    = sym(g_z);
    float* p_st   = sym(g_stats);

    const size_t TOT = (size_t)NB * CC * PP;
    const int EW_BLOCKS4 = (int)((TOT / 4 + 255) / 256);
    const dim3 G13(13, 1, NB);

    zero_stats_kernel<<<3, 256>>>(p_st);

    // --- spatial attention (fused att + apply) ---
    sgemm_bf16<0><<<dim3(13, 2, NB), 256>>>(x, W_qk_s, b_qk_s, p_qk, 64, 96, nullptr);
    spatial_fused<<<NB * TT, 256>>>(x, p_qk, att0s, alphas, p_y);

    // y = BN(conv(y, W_outs)); y = leaky(x + y)   [bias cancels in BN]
    sgemm_bf16<0><<<G13, 256>>>(p_y, W_outs, nullptr, p_conv, 192, 64, p_st + 0);
    bn_apply<<<EW_BLOCKS4, 256>>>((const float4*)p_conv, (const float4*)x,
                                  g_outs, be_outs, p_st + 0, (float4*)p_b1);

    // y = BN(conv(y, W_ffs)); s_out = leaky(x + y)
    sgemm_bf16<0><<<G13, 256>>>(p_b1, W_ffs, nullptr, p_conv, 64, 64, p_st + 128);
    bn_apply<<<EW_BLOCKS4, 256>>>((const float4*)p_conv, (const float4*)x,
                                  g_ffs, be_ffs, p_st + 128, (float4*)p_sout);

    // --- temporal attention ---
    mean_v_kernel<<<(NB * CC * TT + 255) / 256, 256>>>(p_sout, p_xbar);
    sgemm_small<<<dim3(1, 2, NB), 256>>>(p_xbar, W_qk_t, b_qk_t, p_qkt, 64, 128, TT);
    temporal_att<<<NB * 4, 256>>>(p_qkt, al_f, al_b, p_attt);
    temporal_apply_mma<<<dim3(50, 4, NB), 256>>>(p_sout, p_attt, p_z);

    // z = BN(conv(z, W_outt)); z = leaky(t_in + z)
    sgemm_bf16<0><<<G13, 256>>>(p_z, W_outt, nullptr, p_conv, 256, 64, p_st + 256);
    bn_apply<<<EW_BLOCKS4, 256>>>((const float4*)p_conv, (const float4*)p_sout,
                                  g_outt, be_outt, p_st + 256, (float4*)p_b1);

    // z = BN(conv(z, W_fft)); z = leaky(t_in + z)
    sgemm_bf16<0><<<G13, 256>>>(p_b1, W_fft, nullptr, p_conv, 64, 64, p_st + 384);
    bn_apply<<<EW_BLOCKS4, 256>>>((const float4*)p_conv, (const float4*)p_sout,
                                  g_fft, be_fft, p_st + 384, (float4*)p_b2);

    // --- TCN as K=448 GEMM (k = c*7+dt, shifted B rows) ---
    sgemm_bf16<1><<<G13, 256>>>(p_b2, W_tcn, nullptr, p_conv, 448, 64, p_st + 512);
    bn_apply<<<EW_BLOCKS4, 256>>>((const float4*)p_conv, (const float4*)p_b2,
                                  g_tcn, be_tcn, p_st + 512, (float4*)out);
}

// round 17
// speedup vs baseline: 1.4558x; 1.0159x over previous
#include <cuda_runtime.h>
#include <cuda_bf16.h>
#include <math.h>
#include <cstdint>

// ---------------------------------------------------------------------------
// Problem constants
// ---------------------------------------------------------------------------
#define NB   128          // batch N
#define CC   64           // channels C = O
#define TT   64           // T
#define VV   25           // V
#define PP   (TT*VV)      // 1600 positions per (n, channel)
#define SS   3            // spatial heads
#define NTV  (NB*TT*VV)   // 204800 samples per channel for BN

// ---------------------------------------------------------------------------
// Scratch (device globals; no allocation allowed)
// ---------------------------------------------------------------------------
__device__ float g_qk  [ (size_t)NB*96*PP ];        // spatial qk conv out
__device__ float g_y   [ (size_t)NB*192*PP ];       // spatial attended
__device__ float g_conv[ (size_t)NB*CC*PP ];        // generic conv output
__device__ float g_sout[ (size_t)NB*CC*PP ];        // s_out == t_in
__device__ float g_b1  [ (size_t)NB*CC*PP ];
__device__ float g_b2  [ (size_t)NB*CC*PP ];
__device__ float g_xbar[ (size_t)NB*CC*TT ];        // mean over V
__device__ float g_qkt [ (size_t)NB*128*TT ];
__device__ float g_attt[ (size_t)NB*4*TT*TT ];      // 4 slots: f0,f1,b0,b1
__device__ float g_z   [ (size_t)NB*256*PP ];       // temporal attended
__device__ float g_stats[5*128];                    // 5 BNs x (sum[64], sumsq[64])

// ---------------------------------------------------------------------------
// cp.async helpers
// ---------------------------------------------------------------------------
__device__ __forceinline__ unsigned int smem_u32(const void* p)
{
    return (unsigned int)__cvta_generic_to_shared(p);
}
__device__ __forceinline__ void cp16(unsigned int dst, const void* src, int sbytes)
{
    asm volatile("cp.async.cg.shared.global [%0], [%1], 16, %2;"
                 :: "r"(dst), "l"(src), "r"(sbytes));
}
__device__ __forceinline__ void cp4(unsigned int dst, const void* src, int sbytes)
{
    asm volatile("cp.async.ca.shared.global [%0], [%1], 4, %2;"
                 :: "r"(dst), "l"(src), "r"(sbytes));
}
__device__ __forceinline__ void cp_commit()
{
    asm volatile("cp.async.commit_group;");
}
template<int N>
__device__ __forceinline__ void cp_wait()
{
    asm volatile("cp.async.wait_group %0;" :: "n"(N));
}

// ---------------------------------------------------------------------------
// tf32 helpers (used by temporal_apply_mma)
// ---------------------------------------------------------------------------
__device__ __forceinline__ void split_tf32(float x, unsigned& hi, unsigned& lo)
{
    asm("cvt.rna.tf32.f32 %0, %1;" : "=r"(hi) : "f"(x));
    float r = x - __uint_as_float(hi);
    asm("cvt.rna.tf32.f32 %0, %1;" : "=r"(lo) : "f"(r));
}
__device__ __forceinline__ void mma_tf32(float* c, const unsigned* a,
                                         unsigned b0, unsigned b1)
{
    asm volatile(
        "mma.sync.aligned.m16n8k8.row.col.f32.tf32.tf32.f32 "
        "{%0,%1,%2,%3}, {%4,%5,%6,%7}, {%8,%9}, {%0,%1,%2,%3};"
        : "+f"(c[0]), "+f"(c[1]), "+f"(c[2]), "+f"(c[3])
        : "r"(a[0]), "r"(a[1]), "r"(a[2]), "r"(a[3]), "r"(b0), "r"(b1));
}
__device__ __forceinline__ float tanh_fast(float x)
{
    float y;
    asm("tanh.approx.f32 %0, %1;" : "=f"(y) : "f"(x));
    return y;
}

// ---------------------------------------------------------------------------
// bf16 helpers
// ---------------------------------------------------------------------------
__device__ __forceinline__ void split_bf16x2(float x0, float x1,
                                             unsigned& hi, unsigned& lo)
{
    __nv_bfloat162 h = __floats2bfloat162_rn(x0, x1);      // x0 -> low half
    float h0 = __bfloat162float(__low2bfloat16(h));
    float h1 = __bfloat162float(__high2bfloat16(h));
    __nv_bfloat162 l = __floats2bfloat162_rn(x0 - h0, x1 - h1);
    hi = *reinterpret_cast<unsigned*>(&h);
    lo = *reinterpret_cast<unsigned*>(&l);
}
__device__ __forceinline__ void mma_bf16(float* c, const unsigned* a,
                                         unsigned b0, unsigned b1)
{
    asm volatile(
        "mma.sync.aligned.m16n8k16.row.col.f32.bf16.bf16.f32 "
        "{%0,%1,%2,%3}, {%4,%5,%6,%7}, {%8,%9}, {%0,%1,%2,%3};"
        : "+f"(c[0]), "+f"(c[1]), "+f"(c[2]), "+f"(c[3])
        : "r"(a[0]), "r"(a[1]), "r"(a[2]), "r"(a[3]), "r"(b0), "r"(b1));
}

// ---------------------------------------------------------------------------
// Tensor-core GEMM (3x BF16, m16n8k16). Restructured pipeline:
//   - Bhi/Blo SINGLE-buffered (produced+consumed within one tile)
//   - TWO block barriers per k-tile (was three): sync1 after cp_wait
//     (separates prev compute from Bhi overwrite), then split+storeA(nxt),
//     sync2, compute. Per-warp program order guarantees Bs[cur] split reads
//     finish before the it+2 cp.async re-targets that landing buffer.
// Tile: BM=64, BN=128, BK=16; 8 warps 2m x 4n. Fused BN stats.
// Phantom columns (p0+p >= P) stay zero (cp.async zfill) -> clean stats.
// ---------------------------------------------------------------------------
template<int TCN>
__global__ __launch_bounds__(256, 2) void sgemm_bf16(
    const float* __restrict__ X, const float* __restrict__ W,
    const float* __restrict__ bias, float* __restrict__ Y,
    int CIN, int COUT, float* __restrict__ stats)
{
    const int P  = PP;
    const int n  = blockIdx.z;
    const int m0 = blockIdx.y * 64;
    const int p0 = blockIdx.x * 128;
    const float* Xn = X + (size_t)n * (TCN ? 64 : CIN) * P;
    float*       Yn = Y + (size_t)n * COUT * P;

    __shared__ __align__(16) unsigned Ahi[2][64][12];
    __shared__ __align__(16) unsigned Alo[2][64][12];
    __shared__ __align__(16) float    Bs [2][16][132];   // cp.async landing
    __shared__ __align__(16) unsigned Bhi[8][132];       // single buffer
    __shared__ __align__(16) unsigned Blo[8][132];

    float acc[2][4][4];
    #pragma unroll
    for (int i = 0; i < 2; i++)
        #pragma unroll
        for (int j = 0; j < 4; j++)
            #pragma unroll
            for (int c = 0; c < 4; c++) acc[i][j][c] = 0.f;

    const int lane = threadIdx.x & 31;
    const int warp = threadIdx.x >> 5;
    const int g    = lane >> 2;
    const int t4   = lane & 3;
    const int wm   = warp >> 2;   // 0..1
    const int wn   = warp & 3;    // 0..3

    const int nk = CIN / 16;
    unsigned pah[2], pal[2];

    auto issueB = [&](int kt, int buf) {
        const int k0 = kt * 16;
        if (!TCN) {
            #pragma unroll
            for (int i = 0; i < 2; i++) {
                int f = threadIdx.x + i * 256;
                int k = f >> 5, p = (f & 31) * 4;
                bool ok = (p0 + p) < P;
                const float* src = ok ? &Xn[(size_t)(k0 + k) * P + p0 + p] : Xn;
                cp16(smem_u32(&Bs[buf][k][p]), src, ok ? 16 : 0);
            }
        } else {
            #pragma unroll
            for (int i = 0; i < 8; i++) {
                int idx = threadIdx.x + i * 256;
                int k = idx >> 7, p = idx & 127;
                int kk = k0 + k;
                int c = kk / 7, dt = kk % 7;
                int src = p0 + p + (dt - 3) * 25;
                bool ok = (p0 + p) < P && src >= 0 && src < P;
                const float* sp = ok ? &Xn[(size_t)c * P + src] : Xn;
                cp4(smem_u32(&Bs[buf][k][p]), sp, ok ? 4 : 0);
            }
        }
        cp_commit();
    };

    auto stageA = [&](int kt) {
        const int k0 = kt * 16;
        #pragma unroll
        for (int i = 0; i < 2; i++) {
            int pi = threadIdx.x + i * 256;   // 0..511 k-pairs
            int m = pi >> 3, k2 = pi & 7;
            float x0 = 0.f, x1 = 0.f;
            if (m0 + m < COUT) {
                const float* wp = &W[(size_t)(m0 + m) * CIN + k0 + 2 * k2];
                x0 = wp[0]; x1 = wp[1];
            }
            split_bf16x2(x0, x1, pah[i], pal[i]);
        }
    };
    auto storeA = [&](int buf) {
        #pragma unroll
        for (int i = 0; i < 2; i++) {
            int pi = threadIdx.x + i * 256;
            int m = pi >> 3, k2 = pi & 7;
            Ahi[buf][m][k2] = pah[i];
            Alo[buf][m][k2] = pal[i];
        }
    };

    // ---- prologue: tile 0 ----
    stageA(0);
    storeA(0);
    issueB(0, 0);

    for (int it = 0; it < nk; it++) {
        const int cur = it & 1;
        const int nxt = 1 - cur;
        const bool more = (it + 1 < nk);

        if (more) {
            issueB(it + 1, nxt);
            stageA(it + 1);
        }

        if (more) cp_wait<1>(); else cp_wait<0>();
        __syncthreads();   // sync1: Bs[cur] ready; prev compute done

        // ---- split B (cur) into single-buffer Bhi/Blo + store A(nxt) ----
        #pragma unroll
        for (int i = 0; i < 4; i++) {
            int pi = threadIdx.x + i * 256;   // 0..1023
            int k2 = pi >> 7, col = pi & 127;
            unsigned bh, bl;
            split_bf16x2(Bs[cur][2 * k2][col], Bs[cur][2 * k2 + 1][col], bh, bl);
            Bhi[k2][col] = bh;
            Blo[k2][col] = bl;
        }
        if (more) storeA(nxt);
        __syncthreads();   // sync2: Bhi/Blo + A(nxt) visible

        // ---- compute: one m16n8k16 group per tile ----
        unsigned ahi[2][4], alo[2][4];
        #pragma unroll
        for (int mf = 0; mf < 2; mf++) {
            int r = wm * 32 + mf * 16 + g;
            ahi[mf][0] = Ahi[cur][r    ][t4];
            ahi[mf][1] = Ahi[cur][r + 8][t4];
            ahi[mf][2] = Ahi[cur][r    ][t4 + 4];
            ahi[mf][3] = Ahi[cur][r + 8][t4 + 4];
            alo[mf][0] = Alo[cur][r    ][t4];
            alo[mf][1] = Alo[cur][r + 8][t4];
            alo[mf][2] = Alo[cur][r    ][t4 + 4];
            alo[mf][3] = Alo[cur][r + 8][t4 + 4];
        }
        #pragma unroll
        for (int nf = 0; nf < 4; nf++) {
            int col = wn * 32 + nf * 8 + g;
            unsigned bh0 = Bhi[t4    ][col];
            unsigned bh1 = Bhi[t4 + 4][col];
            unsigned bl0 = Blo[t4    ][col];
            unsigned bl1 = Blo[t4 + 4][col];
            #pragma unroll
            for (int mf = 0; mf < 2; mf++) {
                mma_bf16(acc[mf][nf], ahi[mf], bh0, bh1);
                mma_bf16(acc[mf][nf], ahi[mf], bl0, bl1);
                mma_bf16(acc[mf][nf], alo[mf], bh0, bh1);
            }
        }
        // no barrier here: next overwrite of Bhi happens after next sync1
    }

    // ---- epilogue: fragment rows -> global ----
    #pragma unroll
    for (int mf = 0; mf < 2; mf++) {
        #pragma unroll
        for (int half = 0; half < 2; half++) {
            int m = m0 + wm * 32 + mf * 16 + g + half * 8;
            if (m < COUT) {
                float bv = bias ? bias[m] : 0.f;
                #pragma unroll
                for (int nf = 0; nf < 4; nf++) {
                    int p = p0 + wn * 32 + nf * 8 + 2 * t4;
                    if (p < P) {
                        float2 v;
                        v.x = acc[mf][nf][half * 2 + 0] + bv;
                        v.y = acc[mf][nf][half * 2 + 1] + bv;
                        *(float2*)&Yn[(size_t)m * P + p] = v;
                    }
                }
            }
        }
    }
    if (stats) {
        #pragma unroll
        for (int mf = 0; mf < 2; mf++) {
            #pragma unroll
            for (int half = 0; half < 2; half++) {
                int m = m0 + wm * 32 + mf * 16 + g + half * 8;
                float s = 0.f, s2 = 0.f;
                #pragma unroll
                for (int nf = 0; nf < 4; nf++) {
                    float v0 = acc[mf][nf][half * 2 + 0];
                    float v1 = acc[mf][nf][half * 2 + 1];
                    s  += v0 + v1;
                    s2 += v0 * v0 + v1 * v1;
                }
                s  += __shfl_down_sync(0xffffffffu, s,  1, 4);
                s  += __shfl_down_sync(0xffffffffu, s,  2, 4);
                s2 += __shfl_down_sync(0xffffffffu, s2, 1, 4);
                s2 += __shfl_down_sync(0xffffffffu, s2, 2, 4);
                if (t4 == 0 && m < COUT) {
                    atomicAdd(&stats[m], s);
                    atomicAdd(&stats[64 + m], s2);
                }
            }
        }
    }
}

// ---------------------------------------------------------------------------
// Small GEMM for qk_t (P=64 columns only).
// ---------------------------------------------------------------------------
__global__ __launch_bounds__(256) void sgemm_small(
    const float* __restrict__ X, const float* __restrict__ W,
    const float* __restrict__ bias, float* __restrict__ Y,
    int CIN, int COUT, int P)
{
    const int n  = blockIdx.z;
    const int m0 = blockIdx.y * 64;
    const float* Xn = X + (size_t)n * CIN * P;
    float*       Yn = Y + (size_t)n * COUT * P;

    __shared__ float As[16][68];
    __shared__ float Bs[16][68];
    float acc[4][4];
    #pragma unroll
    for (int i = 0; i < 4; i++)
        #pragma unroll
        for (int j = 0; j < 4; j++) acc[i][j] = 0.f;

    const int tx = threadIdx.x & 15;
    const int ty = threadIdx.x >> 4;

    for (int k0 = 0; k0 < CIN; k0 += 16) {
        for (int i = threadIdx.x; i < 64 * 16; i += 256) {
            int m = i >> 4, k = i & 15;
            float w = 0.f;
            if (m0 + m < COUT) w = W[(size_t)(m0 + m) * CIN + k0 + k];
            As[k][m] = w;
        }
        for (int i = threadIdx.x; i < 16 * 64; i += 256) {
            int k = i >> 6, p = i & 63;
            Bs[k][p] = (p < P) ? Xn[(size_t)(k0 + k) * P + p] : 0.f;
        }
        __syncthreads();
        #pragma unroll
        for (int k = 0; k < 16; k++) {
            float a[4], b[4];
            #pragma unroll
            for (int i = 0; i < 4; i++) a[i] = As[k][ty * 4 + i];
            #pragma unroll
            for (int j = 0; j < 4; j++) b[j] = Bs[k][tx * 4 + j];
            #pragma unroll
            for (int i = 0; i < 4; i++)
                #pragma unroll
                for (int j = 0; j < 4; j++) acc[i][j] += a[i] * b[j];
        }
        __syncthreads();
    }
    #pragma unroll
    for (int i = 0; i < 4; i++) {
        int m = m0 + ty * 4 + i;
        if (m < COUT) {
            float bv = bias ? bias[m] : 0.f;
            #pragma unroll
            for (int j = 0; j < 4; j++) {
                int p = tx * 4 + j;
                if (p < P) Yn[(size_t)m * P + p] = acc[i][j] + bv;
            }
        }
    }
}

// ---------------------------------------------------------------------------
// Fused spatial attention + apply: one block per (n,t).
// ---------------------------------------------------------------------------
__global__ __launch_bounds__(256) void spatial_fused(
    const float* __restrict__ x, const float* __restrict__ qk,
    const float* __restrict__ att0, const float* __restrict__ alphas,
    float* __restrict__ y)
{
    int b = blockIdx.x;
    int t = b % TT; int n = b / TT;
    __shared__ __align__(16) float qs[3][16][28];
    __shared__ __align__(16) float ks[3][16][28];
    __shared__ __align__(16) float xs[25][68];    // [u][c]
    __shared__ float as[3][25][26];               // [s][u][v]

    const float* base = qk + (size_t)n * 96 * PP + t * VV;
    for (int i = threadIdx.x; i < 48 * 25; i += 256) {
        int c = i / 25, u = i % 25;
        qs[c >> 4][c & 15][u] = base[(size_t)c * PP + u];
        ks[c >> 4][c & 15][u] = base[(size_t)(48 + c) * PP + u];
    }
    for (int i = threadIdx.x; i < 48 * 3; i += 256) {
        int c = i / 3, u = 25 + i % 3;
        qs[c >> 4][c & 15][u] = 0.f;
        ks[c >> 4][c & 15][u] = 0.f;
    }
    const float* xb = x + (size_t)n * CC * PP + t * VV;
    for (int i = threadIdx.x; i < 64 * 25; i += 256) {
        int c = i / 25, u = i % 25;
        xs[u][c] = xb[(size_t)c * PP + u];
    }
    __syncthreads();

    if (threadIdx.x < 147) {
        int s  = threadIdx.x / 49;
        int r  = threadIdx.x % 49;
        int ug = (r / 7) * 4;
        int vg = (r % 7) * 4;
        float a4[4][4];
        #pragma unroll
        for (int i = 0; i < 4; i++)
            #pragma unroll
            for (int j = 0; j < 4; j++) a4[i][j] = 0.f;
        #pragma unroll
        for (int c = 0; c < 16; c++) {
            float4 qv = *(const float4*)&qs[s][c][ug];
            float4 kv = *(const float4*)&ks[s][c][vg];
            float q[4] = {qv.x, qv.y, qv.z, qv.w};
            float k[4] = {kv.x, kv.y, kv.z, kv.w};
            #pragma unroll
            for (int i = 0; i < 4; i++)
                #pragma unroll
                for (int j = 0; j < 4; j++) a4[i][j] += q[i] * k[j];
        }
        float alpha = alphas[s];
        #pragma unroll
        for (int i = 0; i < 4; i++) {
            int u = ug + i;
            if (u < 25) {
                #pragma unroll
                for (int j = 0; j < 4; j++) {
                    int v = vg + j;
                    if (v < 25)
                        as[s][u][v] = att0[(size_t)s * 625 + u * 25 + v]
                                      + tanh_fast(a4[i][j] * (1.f / 16.f)) * alpha;
                }
            }
        }
    }
    __syncthreads();

    if (threadIdx.x >= 240) return;
    int s  = threadIdx.x / 80;
    int r  = threadIdx.x % 80;
    int cg = r / 5;
    int vg = r % 5;
    float acc[4][5];
    #pragma unroll
    for (int i = 0; i < 4; i++)
        #pragma unroll
        for (int j = 0; j < 5; j++) acc[i][j] = 0.f;
    #pragma unroll
    for (int u = 0; u < 25; u++) {
        float a[4], bb[5];
        *(float4*)a = *(const float4*)&xs[u][cg * 4];
        #pragma unroll
        for (int j = 0; j < 5; j++) bb[j] = as[s][u][vg * 5 + j];
        #pragma unroll
        for (int i = 0; i < 4; i++)
            #pragma unroll
            for (int j = 0; j < 5; j++) acc[i][j] += a[i] * bb[j];
    }
    float* yb = y + (size_t)n * 192 * PP + t * VV;
    #pragma unroll
    for (int i = 0; i < 4; i++) {
        float* yp = yb + (size_t)(s * 64 + cg * 4 + i) * PP + vg * 5;
        #pragma unroll
        for (int j = 0; j < 5; j++) yp[j] = acc[i][j];
    }
}

__global__ void zero_stats_kernel(float* s)
{
    int i = blockIdx.x * blockDim.x + threadIdx.x;
    if (i < 5 * 128) s[i] = 0.f;
}

// out = leaky( res + gamma_c*(conv-mu_c)*rsqrt(var_c+eps) + beta_c ), float4
__global__ __launch_bounds__(256) void bn_apply(
    const float4* __restrict__ conv, const float4* __restrict__ res,
    const float* __restrict__ gamma, const float* __restrict__ beta,
    const float* __restrict__ stats, float4* __restrict__ out)
{
    size_t i = (size_t)blockIdx.x * blockDim.x + threadIdx.x;
    const size_t TOT4 = (size_t)NB * CC * PP / 4;
    if (i >= TOT4) return;
    int c = (int)((i / (PP / 4)) & 63);
    float mu  = stats[c] * (1.f / (float)NTV);
    float var = stats[64 + c] * (1.f / (float)NTV) - mu * mu;
    float g = gamma[c] * rsqrtf(var + 1e-5f);
    float sh = beta[c] - mu * g;
    float4 cv = conv[i], rv = res[i], o;
    float v;
    v = rv.x + cv.x * g + sh; o.x = v > 0.f ? v : 0.1f * v;
    v = rv.y + cv.y * g + sh; o.y = v > 0.f ? v : 0.1f * v;
    v = rv.z + cv.z * g + sh; o.z = v > 0.f ? v : 0.1f * v;
    v = rv.w + cv.w * g + sh; o.w = v > 0.f ? v : 0.1f * v;
    out[i] = o;
}

// ---------------------------------------------------------------------------
// Temporal path
// ---------------------------------------------------------------------------
__global__ void mean_v_kernel(const float* __restrict__ X, float* __restrict__ xb)
{
    int i = blockIdx.x * blockDim.x + threadIdx.x;  // over N*C*T
    if (i >= NB * CC * TT) return;
    const float* p = X + (size_t)i * VV;
    float s = 0.f;
    #pragma unroll
    for (int v = 0; v < VV; v++) s += p[v];
    xb[i] = s * (1.f / (float)VV);
}

__global__ __launch_bounds__(256) void temporal_att(
    const float* __restrict__ qkt, const float* __restrict__ alphaf,
    const float* __restrict__ alphab, float* __restrict__ attt)
{
    int b = blockIdx.x;
    int slot = b & 3; int n = b >> 2;
    int dir = slot >> 1, s = slot & 1;
    int qg = (dir == 0) ? s : 2 + s;
    int kg = (dir == 0) ? 4 + s : 6 + s;
    __shared__ float qs[16][64], ks2[16][64];
    const float* base = qkt + (size_t)n * 128 * TT;
    for (int i = threadIdx.x; i < 16 * 64; i += 256) {
        int c = i >> 6, t = i & 63;
        qs [c][t] = base[(size_t)(qg * 16 + c) * TT + t];
        ks2[c][t] = base[(size_t)(kg * 16 + c) * TT + t];
    }
    __syncthreads();
    float alpha = (dir == 0) ? alphaf[s] : alphab[s];
    float* outp = attt + ((size_t)n * 4 + slot) * TT * TT;
    for (int i = threadIdx.x; i < TT * TT; i += 256) {
        int t = i >> 6, q = i & 63;
        bool keep = (dir == 0) ? (t >= q) : (q >= t);
        float d = 0.f;
        #pragma unroll
        for (int c = 0; c < 16; c++) d += qs[c][t] * ks2[c][q];
        outp[i] = keep ? tanh_fast(d * (1.f / 16.f)) * alpha : 0.f;
    }
}

// ---------------------------------------------------------------------------
// temporal apply as a 3xTF32 MMA GEMM (unchanged)
// ---------------------------------------------------------------------------
__global__ __launch_bounds__(256) void temporal_apply_mma(
    const float* __restrict__ tin, const float* __restrict__ attt,
    float* __restrict__ z)
{
    const int mt   = blockIdx.x;          // 0..49
    const int slot = blockIdx.y;          // 0..3
    const int n    = blockIdx.z;
    const int dir = slot >> 1, s = slot & 1;
    const int chbase = dir * 128 + s * 64;
    const int m0g = mt * 32;

    __shared__ __align__(16) float    As [32][68];   // [m][t]
    __shared__ __align__(16) unsigned Bhi[64][68];   // [t][q]
    __shared__ __align__(16) unsigned Blo[64][68];

    const float* tb = tin + (size_t)n * CC * PP;
    const float* ap = attt + ((size_t)n * 4 + slot) * TT * TT;

    for (int idx = threadIdx.x; idx < 32 * 64; idx += 256) {
        int m = idx & 31, t = idx >> 5;
        int M = m0g + m, c = M / 25, v = M % 25;
        As[m][t] = tb[(size_t)c * PP + t * 25 + v];
    }
    for (int idx = threadIdx.x; idx < 64 * 64; idx += 256) {
        int t = idx >> 6, q = idx & 63;
        unsigned h, l;
        split_tf32(ap[idx], h, l);
        Bhi[t][q] = h; Blo[t][q] = l;
    }
    __syncthreads();

    const int lane = threadIdx.x & 31;
    const int warp = threadIdx.x >> 5;
    const int g    = lane >> 2;
    const int t4   = lane & 3;
    const int wm   = warp >> 2;   // 0..1
    const int wn   = warp & 3;    // 0..3

    float acc[2][4];
    #pragma unroll
    for (int j = 0; j < 2; j++)
        #pragma unroll
        for (int c = 0; c < 4; c++) acc[j][c] = 0.f;

    #pragma unroll
    for (int ks = 0; ks < 8; ks++) {
        const int kk = ks * 8;
        unsigned ahi[4], alo[4];
        int r = wm * 16 + g;
        float a0 = As[r    ][kk + t4];
        float a1 = As[r + 8][kk + t4];
        float a2 = As[r    ][kk + t4 + 4];
        float a3 = As[r + 8][kk + t4 + 4];
        split_tf32(a0, ahi[0], alo[0]);
        split_tf32(a1, ahi[1], alo[1]);
        split_tf32(a2, ahi[2], alo[2]);
        split_tf32(a3, ahi[3], alo[3]);
        #pragma unroll
        for (int nf = 0; nf < 2; nf++) {
            int col = wn * 16 + nf * 8 + g;
            unsigned bh0 = Bhi[kk + t4    ][col];
            unsigned bh1 = Bhi[kk + t4 + 4][col];
            unsigned bl0 = Blo[kk + t4    ][col];
            unsigned bl1 = Blo[kk + t4 + 4][col];
            mma_tf32(acc[nf], ahi, bh0, bh1);
            mma_tf32(acc[nf], ahi, bl0, bl1);
            mma_tf32(acc[nf], alo, bh0, bh1);
        }
    }

    float* zb = z + (size_t)n * 256 * PP;
    #pragma unroll
    for (int half = 0; half < 2; half++) {
        int m = wm * 16 + g + half * 8;
        int M = m0g + m, c = M / 25, v = M % 25;
        float* zp = zb + (size_t)(chbase + c) * PP + v;
        #pragma unroll
        for (int nf = 0; nf < 2; nf++) {
            int q = wn * 16 + nf * 8 + 2 * t4;
            zp[(size_t)q * 25]       = acc[nf][half * 2 + 0];
            zp[(size_t)(q + 1) * 25] = acc[nf][half * 2 + 1];
        }
    }
}

// ---------------------------------------------------------------------------
// Launcher
// ---------------------------------------------------------------------------
static float* sym(const void* symbol)
{
    void* p = nullptr;
    cudaGetSymbolAddress(&p, symbol);
    return (float*)p;
}

extern "C" void kernel_launch(void* const* d_in, const int* in_sizes, int n_in,
                              void* d_out, int out_size)
{
    const float* x       = (const float*)d_in[0];
    const float* att0s   = (const float*)d_in[1];
    const float* alphas  = (const float*)d_in[2];
    const float* W_qk_s  = (const float*)d_in[3];
    const float* b_qk_s  = (const float*)d_in[4];
    const float* W_outs  = (const float*)d_in[5];
    const float* g_outs  = (const float*)d_in[7];
    const float* be_outs = (const float*)d_in[8];
    const float* W_ffs   = (const float*)d_in[9];
    const float* g_ffs   = (const float*)d_in[11];
    const float* be_ffs  = (const float*)d_in[12];
    const float* W_qk_t  = (const float*)d_in[13];
    const float* b_qk_t  = (const float*)d_in[14];
    const float* al_f    = (const float*)d_in[15];
    const float* al_b    = (const float*)d_in[16];
    const float* W_outt  = (const float*)d_in[17];
    const float* g_outt  = (const float*)d_in[19];
    const float* be_outt = (const float*)d_in[20];
    const float* W_fft   = (const float*)d_in[21];
    const float* g_fft   = (const float*)d_in[23];
    const float* be_fft  = (const float*)d_in[24];
    const float* W_tcn   = (const float*)d_in[25];
    const float* g_tcn   = (const float*)d_in[27];
    const float* be_tcn  = (const float*)d_in[28];
    float* out = (float*)d_out;

    float* p_qk   = sym(g_qk);
    float* p_y    = sym(g_y);
    float* p_conv = sym(g_conv);
    float* p_sout = sym(g_sout);
    float* p_b1   = sym(g_b1);
    float* p_b2   = sym(g_b2);
    float* p_xbar = sym(g_xbar);
    float* p_qkt  = sym(g_qkt);
    float* p_attt = sym(g_attt);
    float* p_z    = sym(g_z);
    float* p_st   = sym(g_stats);

    const size_t TOT = (size_t)NB * CC * PP;
    const int EW_BLOCKS4 = (int)((TOT / 4 + 255) / 256);
    const dim3 G13(13, 1, NB);

    zero_stats_kernel<<<3, 256>>>(p_st);

    // --- spatial attention (fused att + apply) ---
    sgemm_bf16<0><<<dim3(13, 2, NB), 256>>>(x, W_qk_s, b_qk_s, p_qk, 64, 96, nullptr);
    spatial_fused<<<NB * TT, 256>>>(x, p_qk, att0s, alphas, p_y);

    // y = BN(conv(y, W_outs)); y = leaky(x + y)   [bias cancels in BN]
    sgemm_bf16<0><<<G13, 256>>>(p_y, W_outs, nullptr, p_conv, 192, 64, p_st + 0);
    bn_apply<<<EW_BLOCKS4, 256>>>((const float4*)p_conv, (const float4*)x,
                                  g_outs, be_outs, p_st + 0, (float4*)p_b1);

    // y = BN(conv(y, W_ffs)); s_out = leaky(x + y)
    sgemm_bf16<0><<<G13, 256>>>(p_b1, W_ffs, nullptr, p_conv, 64, 64, p_st + 128);
    bn_apply<<<EW_BLOCKS4, 256>>>((const float4*)p_conv, (const float4*)x,
                                  g_ffs, be_ffs, p_st + 128, (float4*)p_sout);

    // --- temporal attention ---
    mean_v_kernel<<<(NB * CC * TT + 255) / 256, 256>>>(p_sout, p_xbar);
    sgemm_small<<<dim3(1, 2, NB), 256>>>(p_xbar, W_qk_t, b_qk_t, p_qkt, 64, 128, TT);
    temporal_att<<<NB * 4, 256>>>(p_qkt, al_f, al_b, p_attt);
    temporal_apply_mma<<<dim3(50, 4, NB), 256>>>(p_sout, p_attt, p_z);

    // z = BN(conv(z, W_outt)); z = leaky(t_in + z)
    sgemm_bf16<0><<<G13, 256>>>(p_z, W_outt, nullptr, p_conv, 256, 64, p_st + 256);
    bn_apply<<<EW_BLOCKS4, 256>>>((const float4*)p_conv, (const float4*)p_sout,
                                  g_outt, be_outt, p_st + 256, (float4*)p_b1);

    // z = BN(conv(z, W_fft)); z = leaky(t_in + z)
    sgemm_bf16<0><<<G13, 256>>>(p_b1, W_fft, nullptr, p_conv, 64, 64, p_st + 384);
    bn_apply<<<EW_BLOCKS4, 256>>>((const float4*)p_conv, (const float4*)p_sout,
                                  g_fft, be_fft, p_st + 384, (float4*)p_b2);

    // --- TCN as K=448 GEMM (k = c*7+dt, shifted B rows) ---
    sgemm_bf16<1><<<G13, 256>>>(p_b2, W_tcn, nullptr, p_conv, 448, 64, p_st + 512);
    bn_apply<<<EW_BLOCKS4, 256>>>((const float4*)p_conv, (const float4*)p_b2,
                                  g_tcn, be_tcn, p_st + 512, (float4*)out);
}